// round 13
// baseline (speedup 1.0000x reference)
#include <cuda_runtime.h>
#include <cuda_fp16.h>
#include <math.h>
#include <stdint.h>

// ---------------- problem constants ----------------
#define NES   4096          // E*S
#define VOBS  128
#define KOBS  32
#define H     256
#define LSEQ  32
#define VCOMM 32
#define NL    131072        // NES*LSEQ

// ---------------- device scratch (no allocation allowed) ----------------
__device__ __align__(16) float  g_M[VOBS * KOBS * H];
__device__ __align__(16) float  g_U[32768];
__device__ int    g_idx[NES * KOBS];
__device__ int    g_tok[NES * LSEQ];
__device__ __align__(16) __half g_conv16[NL * H];               // [m=n*32+l][c] half
__device__ __align__(16) float  g_bnPart[512 * 512];
__device__ float  g_bnS[H], g_bnT[H];
__device__ float  g_bxh[768];                                   // bx+bh (r,z), bx (n)
__device__ float  g_bhn[256];                                   // bh (n gate)
__device__ __align__(16) __half g_xproj16[(size_t)NL * 768];    // [m][g*256+j] half (bias folded)
__device__ __align__(16) float  g_h[NES * H];                   // final GRU state
__device__ __align__(16) __half g_W16[2][3 * 65536];            // [0]=Wx^T,[1]=Wh^T flat [768][256]

// ---------------- K: transpose+convert Wx, Wh -> g_W16 half ----------------
__global__ void k_prep(const float* __restrict__ Wx, const float* __restrict__ Wh) {
    __shared__ float t[32][33];
    int mat = blockIdx.z / 3, g = blockIdx.z % 3;
    const float* src = (mat ? Wh : Wx) + g * 65536;   // [k][n]
    __half* dst = g_W16[mat] + g * 65536;             // [n][k]
    int x0 = blockIdx.x * 32, y0 = blockIdx.y * 32;
    int tx = threadIdx.x, ty = threadIdx.y;
    #pragma unroll
    for (int r = 0; r < 32; r += 8)
        t[ty + r][tx] = src[(y0 + ty + r) * 256 + x0 + tx];
    __syncthreads();
    #pragma unroll
    for (int r = 0; r < 32; r += 8)
        dst[(x0 + ty + r) * 256 + y0 + tx] = __float2half(t[tx][ty + r]);
}

// ---------------- K: extract obs indices + comm argmax ----------------
__global__ void k_extract(const float* __restrict__ obs, const float* __restrict__ comm) {
    int m = blockIdx.x;
    int lane = threadIdx.x & 31;
    if (threadIdx.x < 32) {
        const float* o = obs + m * VOBS;
        int base = 0;
        #pragma unroll
        for (int c = 0; c < 4; c++) {
            float v = o[c * 32 + lane];
            unsigned mask = __ballot_sync(0xffffffffu, v > 0.5f);
            if (v > 0.5f) {
                int pos = base + __popc(mask & ((1u << lane) - 1u));
                g_idx[m * KOBS + pos] = c * 32 + lane;
            }
            base += __popc(mask);
        }
    } else {
        int l = lane;
        const float* cm = comm + (m * LSEQ + l) * VCOMM;
        float best = cm[0]; int bi = 0;
        #pragma unroll
        for (int v = 1; v < VCOMM; v++) { float x = cm[v]; if (x > best) { best = x; bi = v; } }
        g_tok[m * LSEQ + l] = bi;
    }
}

// ---------------- K: obs table M ----------------
__global__ void k_obsM(const float* __restrict__ emb, const float* __restrict__ W,
                       const float* __restrict__ a_emb_p) {
    __shared__ float Ps[16][256];
    int k = blockIdx.x, i0 = blockIdx.y * 16;
    float a = a_emb_p[0];
    int tid = threadIdx.x;
    for (int r = tid; r < 16 * 256; r += 256) {
        int i = r >> 8, h = r & 255;
        float v = emb[(i0 + i) * H + h];
        Ps[i][h] = v >= 0.f ? v : a * v;
    }
    __syncthreads();
    float acc[16];
    #pragma unroll
    for (int i = 0; i < 16; i++) acc[i] = 0.f;
    int j = tid;
    const float* Wk = W + (k * H) * H + j;
    for (int h = 0; h < H; h++) {
        float w = Wk[h * H];
        #pragma unroll
        for (int i = 0; i < 16; i++) acc[i] = fmaf(Ps[i][h], w, acc[i]);
    }
    #pragma unroll
    for (int i = 0; i < 16; i++)
        g_M[((i0 + i) * KOBS + k) * H + j] = acc[i];
}

// ---------------- K: conv token table U ----------------
__global__ void k_commU(const float* __restrict__ ce, const float* __restrict__ a_emb_p,
                        const float* __restrict__ w1, const float* __restrict__ w3,
                        const float* __restrict__ w5, const float* __restrict__ w7) {
    extern __shared__ float smc[];
    float* sE = smc;
    float* sW = smc + 8192;
    int g = blockIdx.x, d = blockIdx.y;
    int ks = 2 * g + 1;
    if (d >= ks) return;
    const float* w = (g == 0) ? w1 : (g == 1) ? w3 : (g == 2) ? w5 : w7;
    int tid = threadIdx.x;
    float a = a_emb_p[0];
    for (int v = tid; v < 8192; v += 256) {
        float e = ce[v];
        sE[v] = e >= 0.f ? e : a * e;
    }
    for (int v = tid; v < 16384; v += 256) {
        int cg = v >> 8, h = v & 255;
        sW[cg * 257 + h] = w[(cg * 256 + h) * ks + d];
    }
    __syncthreads();
    int cg = tid & 63, t0 = (tid >> 6) * 8;
    float acc[8];
    #pragma unroll
    for (int t = 0; t < 8; t++) acc[t] = 0.f;
    for (int h = 0; h < 256; h++) {
        float wv = sW[cg * 257 + h];
        #pragma unroll
        for (int t = 0; t < 8; t++) acc[t] = fmaf(sE[(t0 + t) * 256 + h], wv, acc[t]);
    }
    int segoff = (g == 0) ? 0 : (g == 1) ? 2048 : (g == 2) ? 8192 : 18432;
    #pragma unroll
    for (int t = 0; t < 8; t++)
        g_U[segoff + (d * 32 + t0 + t) * 64 + cg] = acc[t];
}

// ---------------- K: conv via half table lookups (fp32 tap accumulation) ----------------
__global__ void k_conv() {
    extern __shared__ float sm[];
    __half* sUh = (__half*)sm;                         // 32768 halves = 65536 B
    float* sRed = (float*)((char*)sm + 65536);         // 2048 floats
    __shared__ int sTok[256];
    int tx = threadIdx.x, ty = threadIdx.y;
    int tid = ty * 64 + tx;
    int n0 = blockIdx.x * 8;
    const float4* gU4 = (const float4*)g_U;
    uint2* sU2 = (uint2*)sUh;
    for (int v = tid; v < 8192; v += 256) {
        float4 f = gU4[v];
        __half2 h0 = __floats2half2_rn(f.x, f.y);
        __half2 h1 = __floats2half2_rn(f.z, f.w);
        uint2 pk; pk.x = *(uint*)&h0; pk.y = *(uint*)&h1;
        sU2[v] = pk;
    }
    if (tid < 256) sTok[tid] = g_tok[n0 * LSEQ + tid];
    __syncthreads();

    int g = tx >> 4, ks = 2 * g + 1, pad = g;
    int seg4 = (g == 0) ? 0 : (g == 1) ? 512 : (g == 2) ? 2048 : 4608;
    int cm = tx & 15;
    float lsum[4] = {0, 0, 0, 0}, lsq[4] = {0, 0, 0, 0};

    for (int half = 0; half < 2; half++) {
        int nl = ty + 4 * half;
        int n = n0 + nl;
        const int* tk = sTok + nl * LSEQ;
        for (int l = 0; l < LSEQ; l++) {
            float a0 = 0.f, a1 = 0.f, a2 = 0.f, a3 = 0.f;
            #pragma unroll
            for (int d = 0; d < 7; d++) {
                int lp = l + d - pad;
                if (d < ks && lp >= 0 && lp < LSEQ) {
                    uint2 u = sU2[seg4 + (d * 32 + tk[lp]) * 16 + cm];
                    float2 f0 = __half22float2(*(__half2*)&u.x);
                    float2 f1 = __half22float2(*(__half2*)&u.y);
                    a0 += f0.x; a1 += f0.y; a2 += f1.x; a3 += f1.y;
                }
            }
            __half2 p0 = __floats2half2_rn(a0, a1);
            __half2 p1 = __floats2half2_rn(a2, a3);
            uint2 pk; pk.x = *(uint*)&p0; pk.y = *(uint*)&p1;
            *(uint2*)&g_conv16[(size_t)(n * LSEQ + l) * 256 + tx * 4] = pk;
            lsum[0] += a0; lsum[1] += a1; lsum[2] += a2; lsum[3] += a3;
            lsq[0] += a0 * a0; lsq[1] += a1 * a1; lsq[2] += a2 * a2; lsq[3] += a3 * a3;
        }
    }
    #pragma unroll
    for (int e = 0; e < 4; e++) {
        sRed[ty * 512 + 4 * tx + e]       = lsum[e];
        sRed[ty * 512 + 256 + 4 * tx + e] = lsq[e];
    }
    __syncthreads();
    if (tid < 256) {
        float s = sRed[tid] + sRed[512 + tid] + sRed[1024 + tid] + sRed[1536 + tid];
        float q = sRed[256 + tid] + sRed[768 + tid] + sRed[1280 + tid] + sRed[1792 + tid];
        g_bnPart[blockIdx.x * 512 + tid]       = s;
        g_bnPart[blockIdx.x * 512 + 256 + tid] = q;
    }
}

// ---------------- K: finalize BN + bias folding (4-way ILP) ----------------
__global__ void k_bnfin(const float* __restrict__ bn_g, const float* __restrict__ bn_b,
                        const float* __restrict__ bx, const float* __restrict__ bh) {
    int c = threadIdx.x;
    double s0 = 0, s1 = 0, s2 = 0, s3 = 0;
    double q0 = 0, q1 = 0, q2 = 0, q3 = 0;
    for (int b = 0; b < 512; b += 4) {
        s0 += (double)g_bnPart[(b + 0) * 512 + c];
        s1 += (double)g_bnPart[(b + 1) * 512 + c];
        s2 += (double)g_bnPart[(b + 2) * 512 + c];
        s3 += (double)g_bnPart[(b + 3) * 512 + c];
        q0 += (double)g_bnPart[(b + 0) * 512 + 256 + c];
        q1 += (double)g_bnPart[(b + 1) * 512 + 256 + c];
        q2 += (double)g_bnPart[(b + 2) * 512 + 256 + c];
        q3 += (double)g_bnPart[(b + 3) * 512 + 256 + c];
    }
    double s = (s0 + s1) + (s2 + s3);
    double q = (q0 + q1) + (q2 + q3);
    double mean = s / (double)NL;
    double var  = q / (double)NL - mean * mean;
    float sc = (float)((double)bn_g[c] / sqrt(var + 1e-5));
    g_bnS[c] = sc;
    g_bnT[c] = bn_b[c] - sc * (float)mean;
    g_bxh[c]       = bx[c]       + bh[c];
    g_bxh[256 + c] = bx[256 + c] + bh[256 + c];
    g_bxh[512 + c] = bx[512 + c];
    g_bhn[c]       = bh[512 + c];
}

// ---------------- K: apply BN+prelu to g_conv16 in place ----------------
__global__ void k_bnapply(const float* __restrict__ cnn_a_p) {
    float ca = cnn_a_p[0];
    uint4* p = (uint4*)g_conv16;
    int base = blockIdx.x * 4096 + threadIdx.x;
    #pragma unroll 4
    for (int k = 0; k < 16; k++) {
        int i = base + k * 256;
        uint4 v = p[i];
        int c0 = (i & 31) * 8;
        uint rv[4] = {v.x, v.y, v.z, v.w};
        #pragma unroll
        for (int u = 0; u < 4; u++) {
            __half2 hv = *(__half2*)&rv[u];
            float2 f = __half22float2(hv);
            int c = c0 + 2 * u;
            float x0 = fmaf(g_bnS[c],     f.x, g_bnT[c]);
            x0 = x0 >= 0.f ? x0 : ca * x0;
            float x1 = fmaf(g_bnS[c + 1], f.y, g_bnT[c + 1]);
            x1 = x1 >= 0.f ? x1 : ca * x1;
            __half2 o = __floats2half2_rn(x0, x1);
            rv[u] = *(uint*)&o;
        }
        v.x = rv[0]; v.y = rv[1]; v.z = rv[2]; v.w = rv[3];
        p[i] = v;
    }
}

// ---------------- K: fp16 mma xproj GEMM, CTA 128x256, warp 64x64, 3-stage pipeline ----------------
__global__ void __launch_bounds__(256, 1) k_xproj16() {
    extern __shared__ __align__(16) __half xsm[];
    __half* As = xsm;                  // [3][128][40]
    __half* Bs = xsm + 3 * 5120;       // [3][256][40]
    int tid = threadIdx.x, lane = tid & 31, wid = tid >> 5;
    int wr = wid & 1, wc = wid >> 1;   // wr 0..1 (64 rows), wc 0..3 (64 cols)
    int m0 = blockIdx.x * 128, nc0 = blockIdx.y * 256;
    const __half* Ag = g_conv16 + (size_t)m0 * 256;
    const __half* Bg = g_W16[0] + (size_t)nc0 * 256;

    float acc[4][8][4];
    #pragma unroll
    for (int i = 0; i < 4; i++)
        #pragma unroll
        for (int j = 0; j < 8; j++)
            #pragma unroll
            for (int q = 0; q < 4; q++) acc[i][j][q] = 0.f;

    #define CPX(s_, k0_) {                                                                 \
        _Pragma("unroll")                                                                  \
        for (int it = 0; it < 2; it++) {                                                   \
            int idx = tid + it * 256;                                                      \
            int row = idx >> 2, kc = idx & 3;                                              \
            uint32_t da = (uint32_t)__cvta_generic_to_shared(                              \
                &As[(s_) * 5120 + row * 40 + kc * 8]);                                     \
            asm volatile("cp.async.cg.shared.global [%0], [%1], 16;"                       \
                :: "r"(da), "l"(Ag + (size_t)row * 256 + (k0_) + kc * 8));                 \
        }                                                                                  \
        _Pragma("unroll")                                                                  \
        for (int it = 0; it < 4; it++) {                                                   \
            int idx = tid + it * 256;                                                      \
            int row = idx >> 2, kc = idx & 3;                                              \
            uint32_t db = (uint32_t)__cvta_generic_to_shared(                              \
                &Bs[(s_) * 10240 + row * 40 + kc * 8]);                                    \
            asm volatile("cp.async.cg.shared.global [%0], [%1], 16;"                       \
                :: "r"(db), "l"(Bg + (size_t)row * 256 + (k0_) + kc * 8));                 \
        }                                                                                  \
        asm volatile("cp.async.commit_group;" ::: "memory");                               \
    }

    CPX(0, 0);
    CPX(1, 32);

    #pragma unroll 1
    for (int c = 0; c < 8; c++) {
        if (c < 7) { asm volatile("cp.async.wait_group 1;" ::: "memory"); }
        else       { asm volatile("cp.async.wait_group 0;" ::: "memory"); }
        __syncthreads();
        if (c < 6) {
            int s2 = (c + 2) % 3;
            CPX(s2, (c + 2) * 32);
        }
        int st = c % 3;
        __half* Ast = As + st * 5120;
        __half* Bst = Bs + st * 10240;
        #pragma unroll
        for (int kk = 0; kk < 2; kk++) {
            uint a[4][4], bb[8][2];
            #pragma unroll
            for (int mi = 0; mi < 4; mi++) {
                uint32_t ad = (uint32_t)__cvta_generic_to_shared(
                    &Ast[(wr * 64 + mi * 16 + (lane & 15)) * 40 + kk * 16 + (lane >> 4) * 8]);
                asm volatile("ldmatrix.sync.aligned.m8n8.x4.shared.b16 {%0,%1,%2,%3}, [%4];"
                    : "=r"(a[mi][0]), "=r"(a[mi][1]), "=r"(a[mi][2]), "=r"(a[mi][3]) : "r"(ad));
            }
            #pragma unroll
            for (int p = 0; p < 4; p++) {
                uint32_t bd = (uint32_t)__cvta_generic_to_shared(
                    &Bst[(wc * 64 + p * 16 + ((lane >> 4) << 3) + (lane & 7)) * 40 +
                         kk * 16 + ((lane >> 3) & 1) * 8]);
                uint r0, r1, r2, r3;
                asm volatile("ldmatrix.sync.aligned.m8n8.x4.shared.b16 {%0,%1,%2,%3}, [%4];"
                    : "=r"(r0), "=r"(r1), "=r"(r2), "=r"(r3) : "r"(bd));
                bb[2 * p][0] = r0; bb[2 * p][1] = r1;
                bb[2 * p + 1][0] = r2; bb[2 * p + 1][1] = r3;
            }
            #pragma unroll
            for (int mi = 0; mi < 4; mi++)
                #pragma unroll
                for (int ni = 0; ni < 8; ni++)
                    asm volatile("mma.sync.aligned.m16n8k16.row.col.f32.f16.f16.f32 "
                        "{%0,%1,%2,%3}, {%4,%5,%6,%7}, {%8,%9}, {%0,%1,%2,%3};"
                        : "+f"(acc[mi][ni][0]), "+f"(acc[mi][ni][1]),
                          "+f"(acc[mi][ni][2]), "+f"(acc[mi][ni][3])
                        : "r"(a[mi][0]), "r"(a[mi][1]), "r"(a[mi][2]), "r"(a[mi][3]),
                          "r"(bb[ni][0]), "r"(bb[ni][1]));
        }
    }

    #pragma unroll
    for (int mi = 0; mi < 4; mi++) {
        int m = m0 + wr * 64 + mi * 16 + (lane >> 2);
        #pragma unroll
        for (int ni = 0; ni < 8; ni++) {
            int n = nc0 + wc * 64 + ni * 8 + (lane & 3) * 2;
            float2 bv = *(const float2*)&g_bxh[n];
            __half2 v0 = __floats2half2_rn(acc[mi][ni][0] + bv.x, acc[mi][ni][1] + bv.y);
            __half2 v1 = __floats2half2_rn(acc[mi][ni][2] + bv.x, acc[mi][ni][3] + bv.y);
            *(__half2*)&g_xproj16[(size_t)m * 768 + n] = v0;
            *(__half2*)&g_xproj16[(size_t)(m + 8) * 768 + n] = v1;
        }
    }
    #undef CPX
}

// ---------------- K: persistent fused GRU — 512 threads / 16 warps ----------------
// R10 sync structure (block barriers, proven 66.6us/4step), but 16 warps for
// latency hiding: warp N-tile = 48 cols, cp.async spread over 512 threads.
template<int STEPS>
__global__ void __launch_bounds__(512, 1) k_rnn() {
    extern __shared__ __align__(16) char rsm[];
    __half* hH = (__half*)rsm;                          // [32][264]      16896 B
    float*  hF = (float*)(rsm + 16896);                 // [32][256]      32768 B
    __half* Gs = (__half*)(rsm + 49664);                // [32][776]      49664 B
    __half* Bt = (__half*)(rsm + 99328);                // [2][768][24]   73728 B
    __half* Xp = (__half*)(rsm + 173056);               // [32][776]      49664 B

    int tid = threadIdx.x, lane = tid & 31, w = tid >> 5;   // w 0..15
    int n0 = blockIdx.x * 32;
    const __half* whR = g_W16[1];                       // [768][256]

    for (int i = tid; i < 32 * 264; i += 512) hH[i] = __float2half(0.f);
    for (int i = tid; i < 32 * 256; i += 512) hF[i] = 0.f;
    __syncthreads();

    // B slice: 768 rows x 2 segs = 1536 copies over 512 threads (3 iters).
    // Xp slab: 32 rows x 96 chunks = 3072 copies over chunks 1..6 (512/chunk).
    #define CPB(bf_, kc_, xstep_, xkc_) {                                                  \
        _Pragma("unroll")                                                                  \
        for (int i = 0; i < 3; i++) {                                                      \
            int idx = tid + i * 512;                                                       \
            int n = idx >> 1, seg = idx & 1;                                               \
            uint32_t dst = (uint32_t)__cvta_generic_to_shared(                             \
                &Bt[(bf_) * 18432 + n * 24 + seg * 8]);                                    \
            const __half* src = whR + (size_t)n * 256 + (kc_) * 16 + seg * 8;              \
            asm volatile("cp.async.cg.shared.global [%0], [%1], 16;" :: "r"(dst), "l"(src)); \
        }                                                                                  \
        if ((xkc_) >= 1 && (xkc_) <= 6) {                                                  \
            int idx = tid + ((xkc_) - 1) * 512;                                            \
            int r = idx / 96, c16 = idx % 96;                                              \
            uint32_t dx = (uint32_t)__cvta_generic_to_shared(&Xp[r * 776 + c16 * 8]);      \
            const __half* sx = g_xproj16 +                                                 \
                ((size_t)(n0 + r) * 32 + (xstep_)) * 768 + c16 * 8;                        \
            asm volatile("cp.async.cg.shared.global [%0], [%1], 16;" :: "r"(dx), "l"(sx)); \
        }                                                                                  \
        asm volatile("cp.async.commit_group;" ::: "memory");                               \
    }

    CPB(0, 0, 0, 0);

    int gr_r = tid >> 4;                // gate row 0..31
    int gs   = (tid & 15) * 4;          // gate col base: j = gs + 64q

    #pragma unroll 1
    for (int l = 0; l < STEPS; l++) {
        float acc[2][6][4];
        #pragma unroll
        for (int mi = 0; mi < 2; mi++)
            #pragma unroll
            for (int ni = 0; ni < 6; ni++)
                #pragma unroll
                for (int q = 0; q < 4; q++) acc[mi][ni][q] = 0.f;

        #pragma unroll 1
        for (int kc = 0; kc < 16; kc++) {
            int gsl = l * 16 + kc;
            int gslp = gsl + 1;
            if (gsl < STEPS * 16 - 1) CPB(gslp & 1, gslp & 15, gslp >> 4, gslp & 15);
            if (gsl < STEPS * 16 - 1) { asm volatile("cp.async.wait_group 1;" ::: "memory"); }
            else                      { asm volatile("cp.async.wait_group 0;" ::: "memory"); }
            __syncthreads();
            int buf = gsl & 1;
            uint af[2][4];
            #pragma unroll
            for (int mi = 0; mi < 2; mi++) {
                uint32_t ad = (uint32_t)__cvta_generic_to_shared(
                    &hH[(mi * 16 + (lane & 15)) * 264 + kc * 16 + (lane >> 4) * 8]);
                asm volatile("ldmatrix.sync.aligned.m8n8.x4.shared.b16 {%0,%1,%2,%3}, [%4];"
                    : "=r"(af[mi][0]), "=r"(af[mi][1]), "=r"(af[mi][2]), "=r"(af[mi][3]) : "r"(ad));
            }
            uint bfr[6][2];
            #pragma unroll
            for (int p = 0; p < 3; p++) {
                uint32_t bd = (uint32_t)__cvta_generic_to_shared(
                    &Bt[buf * 18432 +
                        (w * 48 + p * 16 + ((lane >> 4) << 3) + (lane & 7)) * 24 +
                        ((lane >> 3) & 1) * 8]);
                uint r0, r1, r2, r3;
                asm volatile("ldmatrix.sync.aligned.m8n8.x4.shared.b16 {%0,%1,%2,%3}, [%4];"
                    : "=r"(r0), "=r"(r1), "=r"(r2), "=r"(r3) : "r"(bd));
                bfr[2 * p][0] = r0;     bfr[2 * p][1] = r1;
                bfr[2 * p + 1][0] = r2; bfr[2 * p + 1][1] = r3;
            }
            #pragma unroll
            for (int mi = 0; mi < 2; mi++)
                #pragma unroll
                for (int ni = 0; ni < 6; ni++)
                    asm volatile("mma.sync.aligned.m16n8k16.row.col.f32.f16.f16.f32 "
                        "{%0,%1,%2,%3}, {%4,%5,%6,%7}, {%8,%9}, {%0,%1,%2,%3};"
                        : "+f"(acc[mi][ni][0]), "+f"(acc[mi][ni][1]),
                          "+f"(acc[mi][ni][2]), "+f"(acc[mi][ni][3])
                        : "r"(af[mi][0]), "r"(af[mi][1]), "r"(af[mi][2]), "r"(af[mi][3]),
                          "r"(bfr[ni][0]), "r"(bfr[ni][1]));
        }

        // acc -> Gs (fp16)
        #pragma unroll
        for (int mi = 0; mi < 2; mi++)
            #pragma unroll
            for (int ni = 0; ni < 6; ni++) {
                int r = mi * 16 + (lane >> 2);
                int c = w * 48 + ni * 8 + (lane & 3) * 2;
                __half2 h0 = __floats2half2_rn(acc[mi][ni][0], acc[mi][ni][1]);
                __half2 h1 = __floats2half2_rn(acc[mi][ni][2], acc[mi][ni][3]);
                *(__half2*)&Gs[r * 776 + c]       = h0;
                *(__half2*)&Gs[(r + 8) * 776 + c] = h1;
            }
        __syncthreads();

        // gates: thread -> row gr_r, cols gs + 64q + {0..3}; all operands in smem
        {
            #pragma unroll
            for (int q = 0; q < 4; q++) {
                int j = gs + 64 * q;
                uint2 vr = *(const uint2*)&Xp[gr_r * 776 + j];
                uint2 vz = *(const uint2*)&Xp[gr_r * 776 + 256 + j];
                uint2 vn = *(const uint2*)&Xp[gr_r * 776 + 512 + j];
                uint2 wr2 = *(const uint2*)&Gs[gr_r * 776 + j];
                uint2 wz2 = *(const uint2*)&Gs[gr_r * 776 + 256 + j];
                uint2 wn2 = *(const uint2*)&Gs[gr_r * 776 + 512 + j];
                float2 xr01 = __half22float2(*(__half2*)&vr.x);
                float2 xr23 = __half22float2(*(__half2*)&vr.y);
                float2 xz01 = __half22float2(*(__half2*)&vz.x);
                float2 xz23 = __half22float2(*(__half2*)&vz.y);
                float2 xn01 = __half22float2(*(__half2*)&vn.x);
                float2 xn23 = __half22float2(*(__half2*)&vn.y);
                float2 gr01 = __half22float2(*(__half2*)&wr2.x);
                float2 gr23 = __half22float2(*(__half2*)&wr2.y);
                float2 gz01 = __half22float2(*(__half2*)&wz2.x);
                float2 gz23 = __half22float2(*(__half2*)&wz2.y);
                float2 gn01 = __half22float2(*(__half2*)&wn2.x);
                float2 gn23 = __half22float2(*(__half2*)&wn2.y);
                float4 bn4 = *(const float4*)&g_bhn[j];
                float4 h4  = *(const float4*)&hF[gr_r * 256 + j];
                float xr[4] = {xr01.x, xr01.y, xr23.x, xr23.y};
                float xz[4] = {xz01.x, xz01.y, xz23.x, xz23.y};
                float xn[4] = {xn01.x, xn01.y, xn23.x, xn23.y};
                float gr[4] = {gr01.x, gr01.y, gr23.x, gr23.y};
                float gz[4] = {gz01.x, gz01.y, gz23.x, gz23.y};
                float gn[4] = {gn01.x + bn4.x, gn01.y + bn4.y, gn23.x + bn4.z, gn23.y + bn4.w};
                float hv[4] = {h4.x, h4.y, h4.z, h4.w};
                float hn[4];
                #pragma unroll
                for (int e = 0; e < 4; e++) {
                    float rr = __fdividef(1.f, 1.f + __expf(-(xr[e] + gr[e])));
                    float zz = __fdividef(1.f, 1.f + __expf(-(xz[e] + gz[e])));
                    float arg = xn[e] + rr * gn[e];
                    float e2 = __expf(2.f * arg);
                    float th = 1.f - __fdividef(2.f, e2 + 1.f);
                    hn[e] = th + zz * (hv[e] - th);
                }
                *(float4*)&hF[gr_r * 256 + j] = make_float4(hn[0], hn[1], hn[2], hn[3]);
                __half2 hh0 = __floats2half2_rn(hn[0], hn[1]);
                __half2 hh1 = __floats2half2_rn(hn[2], hn[3]);
                uint2 pk; pk.x = *(uint*)&hh0; pk.y = *(uint*)&hh1;
                *(uint2*)&hH[gr_r * 264 + j] = pk;
            }
        }
        __syncthreads();
    }
    for (int i = tid; i < 8192; i += 512)
        g_h[n0 * 256 + i] = hF[i];
    #undef CPB
}

// ---------------- K: final linear on c-path ----------------
__global__ void k_final(const float* __restrict__ Wl, const float* __restrict__ bl,
                        const float* __restrict__ a1p, const float* __restrict__ a2p,
                        float* __restrict__ out) {
    __shared__ float As[16 * 68];
    __shared__ float Bs[16 * 64];
    int m0 = blockIdx.x * 64;
    int j0 = blockIdx.y * 64;
    float a1 = a1p[0], a2 = a2p[0];
    const float* A = g_h;
    int tid = threadIdx.x;
    int tx = tid & 15, ty = tid >> 4;
    float acc[4][4];
    #pragma unroll
    for (int i = 0; i < 4; i++)
        #pragma unroll
        for (int j = 0; j < 4; j++) acc[i][j] = 0.f;

    for (int k0 = 0; k0 < H; k0 += 16) {
        int row = tid >> 2, segc = tid & 3;
        float4 a4 = *(const float4*)&A[(m0 + row) * H + k0 + 4 * segc];
        float av[4] = {a4.x, a4.y, a4.z, a4.w};
        #pragma unroll
        for (int e = 0; e < 4; e++) {
            float x = av[e];
            As[(4 * segc + e) * 68 + row] = x >= 0.f ? x : a1 * x;
        }
        int rowk = tid >> 4, jc = tid & 15;
        float4 b4 = *(const float4*)&Wl[(k0 + rowk) * H + j0 + 4 * jc];
        *(float4*)&Bs[rowk * 64 + 4 * jc] = b4;
        __syncthreads();
        #pragma unroll
        for (int k = 0; k < 16; k++) {
            float a[4], b[4];
            *(float4*)a = *(const float4*)&As[k * 68 + ty * 4];
            *(float4*)b = *(const float4*)&Bs[k * 64 + tx * 4];
            #pragma unroll
            for (int i = 0; i < 4; i++)
                #pragma unroll
                for (int j = 0; j < 4; j++)
                    acc[i][j] = fmaf(a[i], b[j], acc[i][j]);
        }
        __syncthreads();
    }
    #pragma unroll
    for (int i = 0; i < 4; i++) {
        int m = m0 + ty * 4 + i;
        #pragma unroll
        for (int j = 0; j < 4; j++) {
            int jj = j0 + tx * 4 + j;
            float v = acc[i][j] + bl[jj];
            v = v >= 0.f ? v : a2 * v;
            out[m * 512 + 256 + jj] = v;
        }
    }
}

// ---------------- K: obs output ----------------
__global__ void k_obsout(const float* __restrict__ obs_b, const float* __restrict__ obs_a_p,
                         float* __restrict__ out) {
    int m = blockIdx.x;
    int j = threadIdx.x;
    __shared__ int si[KOBS];
    if (j < KOBS) si[j] = g_idx[m * KOBS + j];
    __syncthreads();
    float acc = obs_b[j];
    #pragma unroll
    for (int k = 0; k < KOBS; k++)
        acc += g_M[(si[k] * KOBS + k) * H + j];
    float a = obs_a_p[0];
    out[m * 512 + j] = acc >= 0.f ? acc : a * acc;
}

// ---------------- host launch ----------------
extern "C" void kernel_launch(void* const* d_in, const int* in_sizes, int n_in,
                              void* d_out, int out_size) {
    const float* obs        = (const float*)d_in[0];
    const float* comm       = (const float*)d_in[1];
    const float* obs_emb    = (const float*)d_in[2];
    const float* obs_a_emb  = (const float*)d_in[3];
    const float* obs_W      = (const float*)d_in[4];
    const float* obs_b      = (const float*)d_in[5];
    const float* obs_a      = (const float*)d_in[6];
    const float* comm_emb   = (const float*)d_in[7];
    const float* comm_a_emb = (const float*)d_in[8];
    const float* cw1        = (const float*)d_in[9];
    const float* cw3        = (const float*)d_in[11];
    const float* cw5        = (const float*)d_in[13];
    const float* cw7        = (const float*)d_in[15];
    const float* bn_g       = (const float*)d_in[17];
    const float* bn_b       = (const float*)d_in[18];
    const float* cnn_a      = (const float*)d_in[19];
    const float* Wx         = (const float*)d_in[20];
    const float* bx         = (const float*)d_in[21];
    const float* Wh         = (const float*)d_in[22];
    const float* bh         = (const float*)d_in[23];
    const float* lin_a1     = (const float*)d_in[24];
    const float* lin_W      = (const float*)d_in[25];
    const float* lin_b      = (const float*)d_in[26];
    const float* lin_a2     = (const float*)d_in[27];
    float* out = (float*)d_out;

    cudaFuncSetAttribute(k_conv,    cudaFuncAttributeMaxDynamicSharedMemorySize, 73728);
    cudaFuncSetAttribute(k_commU,   cudaFuncAttributeMaxDynamicSharedMemorySize, 98560);
    cudaFuncSetAttribute(k_xproj16, cudaFuncAttributeMaxDynamicSharedMemorySize, 92160);
    cudaFuncSetAttribute(k_rnn<4>,  cudaFuncAttributeMaxDynamicSharedMemorySize, 222720);
    cudaFuncSetAttribute(k_rnn<LSEQ>, cudaFuncAttributeMaxDynamicSharedMemorySize, 222720);

    k_prep<<<dim3(8, 8, 6), dim3(32, 8)>>>(Wx, Wh);                  // 0
    k_extract<<<NES, 64>>>(obs, comm);                               // 1
    k_commU<<<dim3(4, 7), 256, 98560>>>(comm_emb, comm_a_emb, cw1, cw3, cw5, cw7); // 2
    // 3: PROFILING CLONE — 4-step k_rnn on stale data; outputs overwritten below.
    k_rnn<4><<<128, 512, 222720>>>();                                // 3 (ncu target)
    k_conv<<<512, dim3(64, 4), 73728>>>();                           // 4
    k_bnfin<<<1, 256>>>(bn_g, bn_b, bx, bh);                         // 5
    k_bnapply<<<1024, 256>>>(cnn_a);                                 // 6
    k_xproj16<<<dim3(1024, 3), 256, 92160>>>();                      // 7
    k_obsM<<<dim3(32, 8), 256>>>(obs_emb, obs_W, obs_a_emb);         // 8
    k_rnn<LSEQ><<<128, 512, 222720>>>();                             // 9
    k_final<<<dim3(64, 4), 256>>>(lin_W, lin_b, lin_a1, lin_a2, out);// 10
    k_obsout<<<NES, 256>>>(obs_b, obs_a, out);                       // 11
}

// round 14
// speedup vs baseline: 1.5439x; 1.5439x over previous
#include <cuda_runtime.h>
#include <cuda_fp16.h>
#include <math.h>
#include <stdint.h>

// ---------------- problem constants ----------------
#define NES   4096          // E*S
#define VOBS  128
#define KOBS  32
#define H     256
#define LSEQ  32
#define VCOMM 32
#define NL    131072        // NES*LSEQ

// ---------------- device scratch (no allocation allowed) ----------------
__device__ __align__(16) float  g_M[VOBS * KOBS * H];
__device__ __align__(16) float  g_U[32768];
__device__ int    g_idx[NES * KOBS];
__device__ int    g_tok[NES * LSEQ];
__device__ __align__(16) __half g_conv16[NL * H];               // [m=n*32+l][c] half
__device__ __align__(16) float  g_bnPart[512 * 512];
__device__ float  g_bnS[H], g_bnT[H];
__device__ float  g_bxh[768];                                   // bx+bh (r,z), bx (n)
__device__ float  g_bhn[256];                                   // bh (n gate)
__device__ __align__(16) __half g_xproj16[(size_t)NL * 768];    // [m][g*256+j] half (bias folded)
__device__ __align__(16) float  g_h[NES * H];                   // final GRU state
__device__ __align__(16) __half g_W16[2][3 * 65536];            // [0]=Wx^T,[1]=Wh^T flat [768][256]

// ---------------- K: transpose+convert Wx, Wh -> g_W16 half ----------------
__global__ void k_prep(const float* __restrict__ Wx, const float* __restrict__ Wh) {
    __shared__ float t[32][33];
    int mat = blockIdx.z / 3, g = blockIdx.z % 3;
    const float* src = (mat ? Wh : Wx) + g * 65536;   // [k][n]
    __half* dst = g_W16[mat] + g * 65536;             // [n][k]
    int x0 = blockIdx.x * 32, y0 = blockIdx.y * 32;
    int tx = threadIdx.x, ty = threadIdx.y;
    #pragma unroll
    for (int r = 0; r < 32; r += 8)
        t[ty + r][tx] = src[(y0 + ty + r) * 256 + x0 + tx];
    __syncthreads();
    #pragma unroll
    for (int r = 0; r < 32; r += 8)
        dst[(x0 + ty + r) * 256 + y0 + tx] = __float2half(t[tx][ty + r]);
}

// ---------------- K: extract obs indices + comm argmax ----------------
__global__ void k_extract(const float* __restrict__ obs, const float* __restrict__ comm) {
    int m = blockIdx.x;
    int lane = threadIdx.x & 31;
    if (threadIdx.x < 32) {
        const float* o = obs + m * VOBS;
        int base = 0;
        #pragma unroll
        for (int c = 0; c < 4; c++) {
            float v = o[c * 32 + lane];
            unsigned mask = __ballot_sync(0xffffffffu, v > 0.5f);
            if (v > 0.5f) {
                int pos = base + __popc(mask & ((1u << lane) - 1u));
                g_idx[m * KOBS + pos] = c * 32 + lane;
            }
            base += __popc(mask);
        }
    } else {
        int l = lane;
        const float* cm = comm + (m * LSEQ + l) * VCOMM;
        float best = cm[0]; int bi = 0;
        #pragma unroll
        for (int v = 1; v < VCOMM; v++) { float x = cm[v]; if (x > best) { best = x; bi = v; } }
        g_tok[m * LSEQ + l] = bi;
    }
}

// ---------------- K: obs table M ----------------
__global__ void k_obsM(const float* __restrict__ emb, const float* __restrict__ W,
                       const float* __restrict__ a_emb_p) {
    __shared__ float Ps[16][256];
    int k = blockIdx.x, i0 = blockIdx.y * 16;
    float a = a_emb_p[0];
    int tid = threadIdx.x;
    for (int r = tid; r < 16 * 256; r += 256) {
        int i = r >> 8, h = r & 255;
        float v = emb[(i0 + i) * H + h];
        Ps[i][h] = v >= 0.f ? v : a * v;
    }
    __syncthreads();
    float acc[16];
    #pragma unroll
    for (int i = 0; i < 16; i++) acc[i] = 0.f;
    int j = tid;
    const float* Wk = W + (k * H) * H + j;
    for (int h = 0; h < H; h++) {
        float w = Wk[h * H];
        #pragma unroll
        for (int i = 0; i < 16; i++) acc[i] = fmaf(Ps[i][h], w, acc[i]);
    }
    #pragma unroll
    for (int i = 0; i < 16; i++)
        g_M[((i0 + i) * KOBS + k) * H + j] = acc[i];
}

// ---------------- K: conv token table U ----------------
__global__ void k_commU(const float* __restrict__ ce, const float* __restrict__ a_emb_p,
                        const float* __restrict__ w1, const float* __restrict__ w3,
                        const float* __restrict__ w5, const float* __restrict__ w7) {
    extern __shared__ float smc[];
    float* sE = smc;
    float* sW = smc + 8192;
    int g = blockIdx.x, d = blockIdx.y;
    int ks = 2 * g + 1;
    if (d >= ks) return;
    const float* w = (g == 0) ? w1 : (g == 1) ? w3 : (g == 2) ? w5 : w7;
    int tid = threadIdx.x;
    float a = a_emb_p[0];
    for (int v = tid; v < 8192; v += 256) {
        float e = ce[v];
        sE[v] = e >= 0.f ? e : a * e;
    }
    for (int v = tid; v < 16384; v += 256) {
        int cg = v >> 8, h = v & 255;
        sW[cg * 257 + h] = w[(cg * 256 + h) * ks + d];
    }
    __syncthreads();
    int cg = tid & 63, t0 = (tid >> 6) * 8;
    float acc[8];
    #pragma unroll
    for (int t = 0; t < 8; t++) acc[t] = 0.f;
    for (int h = 0; h < 256; h++) {
        float wv = sW[cg * 257 + h];
        #pragma unroll
        for (int t = 0; t < 8; t++) acc[t] = fmaf(sE[(t0 + t) * 256 + h], wv, acc[t]);
    }
    int segoff = (g == 0) ? 0 : (g == 1) ? 2048 : (g == 2) ? 8192 : 18432;
    #pragma unroll
    for (int t = 0; t < 8; t++)
        g_U[segoff + (d * 32 + t0 + t) * 64 + cg] = acc[t];
}

// ---------------- K: conv via half table lookups (fp32 tap accumulation) ----------------
__global__ void k_conv() {
    extern __shared__ float sm[];
    __half* sUh = (__half*)sm;                         // 32768 halves = 65536 B
    float* sRed = (float*)((char*)sm + 65536);         // 2048 floats
    __shared__ int sTok[256];
    int tx = threadIdx.x, ty = threadIdx.y;
    int tid = ty * 64 + tx;
    int n0 = blockIdx.x * 8;
    const float4* gU4 = (const float4*)g_U;
    uint2* sU2 = (uint2*)sUh;
    for (int v = tid; v < 8192; v += 256) {
        float4 f = gU4[v];
        __half2 h0 = __floats2half2_rn(f.x, f.y);
        __half2 h1 = __floats2half2_rn(f.z, f.w);
        uint2 pk; pk.x = *(uint*)&h0; pk.y = *(uint*)&h1;
        sU2[v] = pk;
    }
    if (tid < 256) sTok[tid] = g_tok[n0 * LSEQ + tid];
    __syncthreads();

    int g = tx >> 4, ks = 2 * g + 1, pad = g;
    int seg4 = (g == 0) ? 0 : (g == 1) ? 512 : (g == 2) ? 2048 : 4608;
    int cm = tx & 15;
    float lsum[4] = {0, 0, 0, 0}, lsq[4] = {0, 0, 0, 0};

    for (int half = 0; half < 2; half++) {
        int nl = ty + 4 * half;
        int n = n0 + nl;
        const int* tk = sTok + nl * LSEQ;
        for (int l = 0; l < LSEQ; l++) {
            float a0 = 0.f, a1 = 0.f, a2 = 0.f, a3 = 0.f;
            #pragma unroll
            for (int d = 0; d < 7; d++) {
                int lp = l + d - pad;
                if (d < ks && lp >= 0 && lp < LSEQ) {
                    uint2 u = sU2[seg4 + (d * 32 + tk[lp]) * 16 + cm];
                    float2 f0 = __half22float2(*(__half2*)&u.x);
                    float2 f1 = __half22float2(*(__half2*)&u.y);
                    a0 += f0.x; a1 += f0.y; a2 += f1.x; a3 += f1.y;
                }
            }
            __half2 p0 = __floats2half2_rn(a0, a1);
            __half2 p1 = __floats2half2_rn(a2, a3);
            uint2 pk; pk.x = *(uint*)&p0; pk.y = *(uint*)&p1;
            *(uint2*)&g_conv16[(size_t)(n * LSEQ + l) * 256 + tx * 4] = pk;
            lsum[0] += a0; lsum[1] += a1; lsum[2] += a2; lsum[3] += a3;
            lsq[0] += a0 * a0; lsq[1] += a1 * a1; lsq[2] += a2 * a2; lsq[3] += a3 * a3;
        }
    }
    #pragma unroll
    for (int e = 0; e < 4; e++) {
        sRed[ty * 512 + 4 * tx + e]       = lsum[e];
        sRed[ty * 512 + 256 + 4 * tx + e] = lsq[e];
    }
    __syncthreads();
    if (tid < 256) {
        float s = sRed[tid] + sRed[512 + tid] + sRed[1024 + tid] + sRed[1536 + tid];
        float q = sRed[256 + tid] + sRed[768 + tid] + sRed[1280 + tid] + sRed[1792 + tid];
        g_bnPart[blockIdx.x * 512 + tid]       = s;
        g_bnPart[blockIdx.x * 512 + 256 + tid] = q;
    }
}

// ---------------- K: finalize BN + bias folding (4-way ILP) ----------------
__global__ void k_bnfin(const float* __restrict__ bn_g, const float* __restrict__ bn_b,
                        const float* __restrict__ bx, const float* __restrict__ bh) {
    int c = threadIdx.x;
    double s0 = 0, s1 = 0, s2 = 0, s3 = 0;
    double q0 = 0, q1 = 0, q2 = 0, q3 = 0;
    for (int b = 0; b < 512; b += 4) {
        s0 += (double)g_bnPart[(b + 0) * 512 + c];
        s1 += (double)g_bnPart[(b + 1) * 512 + c];
        s2 += (double)g_bnPart[(b + 2) * 512 + c];
        s3 += (double)g_bnPart[(b + 3) * 512 + c];
        q0 += (double)g_bnPart[(b + 0) * 512 + 256 + c];
        q1 += (double)g_bnPart[(b + 1) * 512 + 256 + c];
        q2 += (double)g_bnPart[(b + 2) * 512 + 256 + c];
        q3 += (double)g_bnPart[(b + 3) * 512 + 256 + c];
    }
    double s = (s0 + s1) + (s2 + s3);
    double q = (q0 + q1) + (q2 + q3);
    double mean = s / (double)NL;
    double var  = q / (double)NL - mean * mean;
    float sc = (float)((double)bn_g[c] / sqrt(var + 1e-5));
    g_bnS[c] = sc;
    g_bnT[c] = bn_b[c] - sc * (float)mean;
    g_bxh[c]       = bx[c]       + bh[c];
    g_bxh[256 + c] = bx[256 + c] + bh[256 + c];
    g_bxh[512 + c] = bx[512 + c];
    g_bhn[c]       = bh[512 + c];
}

// ---------------- K: apply BN+prelu to g_conv16 in place ----------------
__global__ void k_bnapply(const float* __restrict__ cnn_a_p) {
    float ca = cnn_a_p[0];
    uint4* p = (uint4*)g_conv16;
    int base = blockIdx.x * 4096 + threadIdx.x;
    #pragma unroll 4
    for (int k = 0; k < 16; k++) {
        int i = base + k * 256;
        uint4 v = p[i];
        int c0 = (i & 31) * 8;
        uint rv[4] = {v.x, v.y, v.z, v.w};
        #pragma unroll
        for (int u = 0; u < 4; u++) {
            __half2 hv = *(__half2*)&rv[u];
            float2 f = __half22float2(hv);
            int c = c0 + 2 * u;
            float x0 = fmaf(g_bnS[c],     f.x, g_bnT[c]);
            x0 = x0 >= 0.f ? x0 : ca * x0;
            float x1 = fmaf(g_bnS[c + 1], f.y, g_bnT[c + 1]);
            x1 = x1 >= 0.f ? x1 : ca * x1;
            __half2 o = __floats2half2_rn(x0, x1);
            rv[u] = *(uint*)&o;
        }
        v.x = rv[0]; v.y = rv[1]; v.z = rv[2]; v.w = rv[3];
        p[i] = v;
    }
}

// ---------------- K: fp16 mma xproj GEMM, CTA 128x256, warp 64x64, 3-stage pipeline ----------------
__global__ void __launch_bounds__(256, 1) k_xproj16() {
    extern __shared__ __align__(16) __half xsm[];
    __half* As = xsm;                  // [3][128][40]
    __half* Bs = xsm + 3 * 5120;       // [3][256][40]
    int tid = threadIdx.x, lane = tid & 31, wid = tid >> 5;
    int wr = wid & 1, wc = wid >> 1;   // wr 0..1 (64 rows), wc 0..3 (64 cols)
    int m0 = blockIdx.x * 128, nc0 = blockIdx.y * 256;
    const __half* Ag = g_conv16 + (size_t)m0 * 256;
    const __half* Bg = g_W16[0] + (size_t)nc0 * 256;

    float acc[4][8][4];
    #pragma unroll
    for (int i = 0; i < 4; i++)
        #pragma unroll
        for (int j = 0; j < 8; j++)
            #pragma unroll
            for (int q = 0; q < 4; q++) acc[i][j][q] = 0.f;

    #define CPX(s_, k0_) {                                                                 \
        _Pragma("unroll")                                                                  \
        for (int it = 0; it < 2; it++) {                                                   \
            int idx = tid + it * 256;                                                      \
            int row = idx >> 2, kc = idx & 3;                                              \
            uint32_t da = (uint32_t)__cvta_generic_to_shared(                              \
                &As[(s_) * 5120 + row * 40 + kc * 8]);                                     \
            asm volatile("cp.async.cg.shared.global [%0], [%1], 16;"                       \
                :: "r"(da), "l"(Ag + (size_t)row * 256 + (k0_) + kc * 8));                 \
        }                                                                                  \
        _Pragma("unroll")                                                                  \
        for (int it = 0; it < 4; it++) {                                                   \
            int idx = tid + it * 256;                                                      \
            int row = idx >> 2, kc = idx & 3;                                              \
            uint32_t db = (uint32_t)__cvta_generic_to_shared(                              \
                &Bs[(s_) * 10240 + row * 40 + kc * 8]);                                    \
            asm volatile("cp.async.cg.shared.global [%0], [%1], 16;"                       \
                :: "r"(db), "l"(Bg + (size_t)row * 256 + (k0_) + kc * 8));                 \
        }                                                                                  \
        asm volatile("cp.async.commit_group;" ::: "memory");                               \
    }

    CPX(0, 0);
    CPX(1, 32);

    #pragma unroll 1
    for (int c = 0; c < 8; c++) {
        if (c < 7) { asm volatile("cp.async.wait_group 1;" ::: "memory"); }
        else       { asm volatile("cp.async.wait_group 0;" ::: "memory"); }
        __syncthreads();
        if (c < 6) {
            int s2 = (c + 2) % 3;
            CPX(s2, (c + 2) * 32);
        }
        int st = c % 3;
        __half* Ast = As + st * 5120;
        __half* Bst = Bs + st * 10240;
        #pragma unroll
        for (int kk = 0; kk < 2; kk++) {
            uint a[4][4], bb[8][2];
            #pragma unroll
            for (int mi = 0; mi < 4; mi++) {
                uint32_t ad = (uint32_t)__cvta_generic_to_shared(
                    &Ast[(wr * 64 + mi * 16 + (lane & 15)) * 40 + kk * 16 + (lane >> 4) * 8]);
                asm volatile("ldmatrix.sync.aligned.m8n8.x4.shared.b16 {%0,%1,%2,%3}, [%4];"
                    : "=r"(a[mi][0]), "=r"(a[mi][1]), "=r"(a[mi][2]), "=r"(a[mi][3]) : "r"(ad));
            }
            #pragma unroll
            for (int p = 0; p < 4; p++) {
                uint32_t bd = (uint32_t)__cvta_generic_to_shared(
                    &Bst[(wc * 64 + p * 16 + ((lane >> 4) << 3) + (lane & 7)) * 40 +
                         kk * 16 + ((lane >> 3) & 1) * 8]);
                uint r0, r1, r2, r3;
                asm volatile("ldmatrix.sync.aligned.m8n8.x4.shared.b16 {%0,%1,%2,%3}, [%4];"
                    : "=r"(r0), "=r"(r1), "=r"(r2), "=r"(r3) : "r"(bd));
                bb[2 * p][0] = r0; bb[2 * p][1] = r1;
                bb[2 * p + 1][0] = r2; bb[2 * p + 1][1] = r3;
            }
            #pragma unroll
            for (int mi = 0; mi < 4; mi++)
                #pragma unroll
                for (int ni = 0; ni < 8; ni++)
                    asm volatile("mma.sync.aligned.m16n8k16.row.col.f32.f16.f16.f32 "
                        "{%0,%1,%2,%3}, {%4,%5,%6,%7}, {%8,%9}, {%0,%1,%2,%3};"
                        : "+f"(acc[mi][ni][0]), "+f"(acc[mi][ni][1]),
                          "+f"(acc[mi][ni][2]), "+f"(acc[mi][ni][3])
                        : "r"(a[mi][0]), "r"(a[mi][1]), "r"(a[mi][2]), "r"(a[mi][3]),
                          "r"(bb[ni][0]), "r"(bb[ni][1]));
        }
    }

    #pragma unroll
    for (int mi = 0; mi < 4; mi++) {
        int m = m0 + wr * 64 + mi * 16 + (lane >> 2);
        #pragma unroll
        for (int ni = 0; ni < 8; ni++) {
            int n = nc0 + wc * 64 + ni * 8 + (lane & 3) * 2;
            float2 bv = *(const float2*)&g_bxh[n];
            __half2 v0 = __floats2half2_rn(acc[mi][ni][0] + bv.x, acc[mi][ni][1] + bv.y);
            __half2 v1 = __floats2half2_rn(acc[mi][ni][2] + bv.x, acc[mi][ni][3] + bv.y);
            *(__half2*)&g_xproj16[(size_t)m * 768 + n] = v0;
            *(__half2*)&g_xproj16[(size_t)(m + 8) * 768 + n] = v1;
        }
    }
    #undef CPX
}

// ---------------- K: persistent fused GRU — R10 body + 3-deep Bt pipeline + h in registers ----------------
// 256 threads / 8 warps (proven best). Bt triple-buffered, prefetch distance 2
// (wait_group 2) so the per-chunk barrier pays no exposed L2 latency. h fp32
// carry lives in gate-thread registers (hreg); only fp16 hH in smem for MMA.
template<int STEPS>
__global__ void __launch_bounds__(256, 1) k_rnn() {
    extern __shared__ __align__(16) char rsm[];
    __half* hH = (__half*)rsm;                          // [32][264]        16896 B
    __half* Gs = (__half*)(rsm + 16896);                // [32][776] fp16   49664 B
    __half* Bt = (__half*)(rsm + 66560);                // [3][768][24]    110592 B
    __half* Xp = (__half*)(rsm + 177152);               // [32][776] fp16   49664 B
    // total 226816 B

    int tid = threadIdx.x, lane = tid & 31, w = tid >> 5;
    int n0 = blockIdx.x * 32;
    const __half* whR = g_W16[1];                       // [768][256]

    for (int i = tid; i < 32 * 264; i += 256) hH[i] = __float2half(0.f);
    __syncthreads();

    int gr_r = tid >> 3;                // gate row 0..31
    int gs   = (tid & 7) * 4;           // gate col base: j = gs + 32q
    float hreg[32];                     // fp32 h carry: hreg[4q+e] = h[gr_r][gs+32q+e]
    #pragma unroll
    for (int i = 0; i < 32; i++) hreg[i] = 0.f;

    // Group g_: B K-slice (g_&15) -> buffer (g_%3); Xp slab chunk (g_&15)-2 of
    // step (g_>>4) when (g_&15) in 2..13 (issued strictly inside step g_>>4).
    #define CPB(g_) {                                                                      \
        int bf_ = (g_) % 3, kcs_ = (g_) & 15;                                              \
        _Pragma("unroll")                                                                  \
        for (int i = 0; i < 6; i++) {                                                      \
            int idx = tid + i * 256;                                                       \
            int n = idx >> 1, seg = idx & 1;                                               \
            uint32_t dst = (uint32_t)__cvta_generic_to_shared(                             \
                &Bt[bf_ * 18432 + n * 24 + seg * 8]);                                      \
            const __half* src = whR + (size_t)n * 256 + kcs_ * 16 + seg * 8;               \
            asm volatile("cp.async.cg.shared.global [%0], [%1], 16;" :: "r"(dst), "l"(src)); \
        }                                                                                  \
        if (kcs_ >= 2 && kcs_ <= 13) {                                                     \
            int idx = tid + (kcs_ - 2) * 256;                                              \
            int r = idx / 96, c16 = idx % 96;                                              \
            uint32_t dx = (uint32_t)__cvta_generic_to_shared(&Xp[r * 776 + c16 * 8]);      \
            const __half* sx = g_xproj16 +                                                 \
                ((size_t)(n0 + r) * 32 + ((g_) >> 4)) * 768 + c16 * 8;                     \
            asm volatile("cp.async.cg.shared.global [%0], [%1], 16;" :: "r"(dx), "l"(sx)); \
        }                                                                                  \
        asm volatile("cp.async.commit_group;" ::: "memory");                               \
    }

    CPB(0);
    CPB(1);

    #pragma unroll 1
    for (int l = 0; l < STEPS; l++) {
        float acc[2][12][4];
        #pragma unroll
        for (int mi = 0; mi < 2; mi++)
            #pragma unroll
            for (int ni = 0; ni < 12; ni++)
                #pragma unroll
                for (int q = 0; q < 4; q++) acc[mi][ni][q] = 0.f;

        #pragma unroll 1
        for (int kc = 0; kc < 16; kc++) {
            int gsl = l * 16 + kc;
            if (gsl + 2 < STEPS * 16) {
                CPB(gsl + 2);
                asm volatile("cp.async.wait_group 2;" ::: "memory");
            } else if (gsl + 1 < STEPS * 16) {
                asm volatile("cp.async.wait_group 1;" ::: "memory");
            } else {
                asm volatile("cp.async.wait_group 0;" ::: "memory");
            }
            __syncthreads();
            int buf = gsl % 3;
            uint af[2][4];
            #pragma unroll
            for (int mi = 0; mi < 2; mi++) {
                uint32_t ad = (uint32_t)__cvta_generic_to_shared(
                    &hH[(mi * 16 + (lane & 15)) * 264 + kc * 16 + (lane >> 4) * 8]);
                asm volatile("ldmatrix.sync.aligned.m8n8.x4.shared.b16 {%0,%1,%2,%3}, [%4];"
                    : "=r"(af[mi][0]), "=r"(af[mi][1]), "=r"(af[mi][2]), "=r"(af[mi][3]) : "r"(ad));
            }
            uint bfr[12][2];
            #pragma unroll
            for (int p = 0; p < 6; p++) {
                uint32_t bd = (uint32_t)__cvta_generic_to_shared(
                    &Bt[buf * 18432 +
                        (w * 96 + p * 16 + ((lane >> 4) << 3) + (lane & 7)) * 24 +
                        ((lane >> 3) & 1) * 8]);
                uint r0, r1, r2, r3;
                asm volatile("ldmatrix.sync.aligned.m8n8.x4.shared.b16 {%0,%1,%2,%3}, [%4];"
                    : "=r"(r0), "=r"(r1), "=r"(r2), "=r"(r3) : "r"(bd));
                bfr[2 * p][0] = r0;     bfr[2 * p][1] = r1;
                bfr[2 * p + 1][0] = r2; bfr[2 * p + 1][1] = r3;
            }
            #pragma unroll
            for (int mi = 0; mi < 2; mi++)
                #pragma unroll
                for (int ni = 0; ni < 12; ni++)
                    asm volatile("mma.sync.aligned.m16n8k16.row.col.f32.f16.f16.f32 "
                        "{%0,%1,%2,%3}, {%4,%5,%6,%7}, {%8,%9}, {%0,%1,%2,%3};"
                        : "+f"(acc[mi][ni][0]), "+f"(acc[mi][ni][1]),
                          "+f"(acc[mi][ni][2]), "+f"(acc[mi][ni][3])
                        : "r"(af[mi][0]), "r"(af[mi][1]), "r"(af[mi][2]), "r"(af[mi][3]),
                          "r"(bfr[ni][0]), "r"(bfr[ni][1]));
        }

        // acc -> Gs (fp16)
        #pragma unroll
        for (int mi = 0; mi < 2; mi++)
            #pragma unroll
            for (int ni = 0; ni < 12; ni++) {
                int r = mi * 16 + (lane >> 2);
                int c = w * 96 + ni * 8 + (lane & 3) * 2;
                __half2 h0 = __floats2half2_rn(acc[mi][ni][0], acc[mi][ni][1]);
                __half2 h1 = __floats2half2_rn(acc[mi][ni][2], acc[mi][ni][3]);
                *(__half2*)&Gs[r * 776 + c]       = h0;
                *(__half2*)&Gs[(r + 8) * 776 + c] = h1;
            }
        __syncthreads();    // publish Gs; Xp slab fully drained by kc-loop waits

        // gates: thread -> row gr_r, cols gs + 32q + {0..3}; h in registers
        {
            #pragma unroll
            for (int q = 0; q < 8; q++) {
                int j = gs + 32 * q;
                uint2 vr = *(const uint2*)&Xp[gr_r * 776 + j];
                uint2 vz = *(const uint2*)&Xp[gr_r * 776 + 256 + j];
                uint2 vn = *(const uint2*)&Xp[gr_r * 776 + 512 + j];
                uint2 wr2 = *(const uint2*)&Gs[gr_r * 776 + j];
                uint2 wz2 = *(const uint2*)&Gs[gr_r * 776 + 256 + j];
                uint2 wn2 = *(const uint2*)&Gs[gr_r * 776 + 512 + j];
                float2 xr01 = __half22float2(*(__half2*)&vr.x);
                float2 xr23 = __half22float2(*(__half2*)&vr.y);
                float2 xz01 = __half22float2(*(__half2*)&vz.x);
                float2 xz23 = __half22float2(*(__half2*)&vz.y);
                float2 xn01 = __half22float2(*(__half2*)&vn.x);
                float2 xn23 = __half22float2(*(__half2*)&vn.y);
                float2 gr01 = __half22float2(*(__half2*)&wr2.x);
                float2 gr23 = __half22float2(*(__half2*)&wr2.y);
                float2 gz01 = __half22float2(*(__half2*)&wz2.x);
                float2 gz23 = __half22float2(*(__half2*)&wz2.y);
                float2 gn01 = __half22float2(*(__half2*)&wn2.x);
                float2 gn23 = __half22float2(*(__half2*)&wn2.y);
                float4 bn4 = *(const float4*)&g_bhn[j];
                float xr[4] = {xr01.x, xr01.y, xr23.x, xr23.y};
                float xz[4] = {xz01.x, xz01.y, xz23.x, xz23.y};
                float xn[4] = {xn01.x, xn01.y, xn23.x, xn23.y};
                float gr[4] = {gr01.x, gr01.y, gr23.x, gr23.y};
                float gz[4] = {gz01.x, gz01.y, gz23.x, gz23.y};
                float gn[4] = {gn01.x + bn4.x, gn01.y + bn4.y, gn23.x + bn4.z, gn23.y + bn4.w};
                float hn[4];
                #pragma unroll
                for (int e = 0; e < 4; e++) {
                    float h = hreg[4 * q + e];
                    float rr = __fdividef(1.f, 1.f + __expf(-(xr[e] + gr[e])));
                    float zz = __fdividef(1.f, 1.f + __expf(-(xz[e] + gz[e])));
                    float arg = xn[e] + rr * gn[e];
                    float e2 = __expf(2.f * arg);
                    float th = 1.f - __fdividef(2.f, e2 + 1.f);
                    hn[e] = th + zz * (h - th);
                    hreg[4 * q + e] = hn[e];
                }
                __half2 hh0 = __floats2half2_rn(hn[0], hn[1]);
                __half2 hh1 = __floats2half2_rn(hn[2], hn[3]);
                uint2 pk; pk.x = *(uint*)&hh0; pk.y = *(uint*)&hh1;
                *(uint2*)&hH[gr_r * 264 + j] = pk;
            }
        }
        __syncthreads();    // publish hH for next step's ldmatrix
    }
    // write final fp32 state from registers
    #pragma unroll
    for (int q = 0; q < 8; q++) {
        *(float4*)&g_h[(size_t)(n0 + gr_r) * 256 + gs + 32 * q] =
            make_float4(hreg[4 * q], hreg[4 * q + 1], hreg[4 * q + 2], hreg[4 * q + 3]);
    }
    #undef CPB
}

// ---------------- K: final linear on c-path ----------------
__global__ void k_final(const float* __restrict__ Wl, const float* __restrict__ bl,
                        const float* __restrict__ a1p, const float* __restrict__ a2p,
                        float* __restrict__ out) {
    __shared__ float As[16 * 68];
    __shared__ float Bs[16 * 64];
    int m0 = blockIdx.x * 64;
    int j0 = blockIdx.y * 64;
    float a1 = a1p[0], a2 = a2p[0];
    const float* A = g_h;
    int tid = threadIdx.x;
    int tx = tid & 15, ty = tid >> 4;
    float acc[4][4];
    #pragma unroll
    for (int i = 0; i < 4; i++)
        #pragma unroll
        for (int j = 0; j < 4; j++) acc[i][j] = 0.f;

    for (int k0 = 0; k0 < H; k0 += 16) {
        int row = tid >> 2, segc = tid & 3;
        float4 a4 = *(const float4*)&A[(m0 + row) * H + k0 + 4 * segc];
        float av[4] = {a4.x, a4.y, a4.z, a4.w};
        #pragma unroll
        for (int e = 0; e < 4; e++) {
            float x = av[e];
            As[(4 * segc + e) * 68 + row] = x >= 0.f ? x : a1 * x;
        }
        int rowk = tid >> 4, jc = tid & 15;
        float4 b4 = *(const float4*)&Wl[(k0 + rowk) * H + j0 + 4 * jc];
        *(float4*)&Bs[rowk * 64 + 4 * jc] = b4;
        __syncthreads();
        #pragma unroll
        for (int k = 0; k < 16; k++) {
            float a[4], b[4];
            *(float4*)a = *(const float4*)&As[k * 68 + ty * 4];
            *(float4*)b = *(const float4*)&Bs[k * 64 + tx * 4];
            #pragma unroll
            for (int i = 0; i < 4; i++)
                #pragma unroll
                for (int j = 0; j < 4; j++)
                    acc[i][j] = fmaf(a[i], b[j], acc[i][j]);
        }
        __syncthreads();
    }
    #pragma unroll
    for (int i = 0; i < 4; i++) {
        int m = m0 + ty * 4 + i;
        #pragma unroll
        for (int j = 0; j < 4; j++) {
            int jj = j0 + tx * 4 + j;
            float v = acc[i][j] + bl[jj];
            v = v >= 0.f ? v : a2 * v;
            out[m * 512 + 256 + jj] = v;
        }
    }
}

// ---------------- K: obs output ----------------
__global__ void k_obsout(const float* __restrict__ obs_b, const float* __restrict__ obs_a_p,
                         float* __restrict__ out) {
    int m = blockIdx.x;
    int j = threadIdx.x;
    __shared__ int si[KOBS];
    if (j < KOBS) si[j] = g_idx[m * KOBS + j];
    __syncthreads();
    float acc = obs_b[j];
    #pragma unroll
    for (int k = 0; k < KOBS; k++)
        acc += g_M[(si[k] * KOBS + k) * H + j];
    float a = obs_a_p[0];
    out[m * 512 + j] = acc >= 0.f ? acc : a * acc;
}

// ---------------- host launch ----------------
extern "C" void kernel_launch(void* const* d_in, const int* in_sizes, int n_in,
                              void* d_out, int out_size) {
    const float* obs        = (const float*)d_in[0];
    const float* comm       = (const float*)d_in[1];
    const float* obs_emb    = (const float*)d_in[2];
    const float* obs_a_emb  = (const float*)d_in[3];
    const float* obs_W      = (const float*)d_in[4];
    const float* obs_b      = (const float*)d_in[5];
    const float* obs_a      = (const float*)d_in[6];
    const float* comm_emb   = (const float*)d_in[7];
    const float* comm_a_emb = (const float*)d_in[8];
    const float* cw1        = (const float*)d_in[9];
    const float* cw3        = (const float*)d_in[11];
    const float* cw5        = (const float*)d_in[13];
    const float* cw7        = (const float*)d_in[15];
    const float* bn_g       = (const float*)d_in[17];
    const float* bn_b       = (const float*)d_in[18];
    const float* cnn_a      = (const float*)d_in[19];
    const float* Wx         = (const float*)d_in[20];
    const float* bx         = (const float*)d_in[21];
    const float* Wh         = (const float*)d_in[22];
    const float* bh         = (const float*)d_in[23];
    const float* lin_a1     = (const float*)d_in[24];
    const float* lin_W      = (const float*)d_in[25];
    const float* lin_b      = (const float*)d_in[26];
    const float* lin_a2     = (const float*)d_in[27];
    float* out = (float*)d_out;

    cudaFuncSetAttribute(k_conv,    cudaFuncAttributeMaxDynamicSharedMemorySize, 73728);
    cudaFuncSetAttribute(k_commU,   cudaFuncAttributeMaxDynamicSharedMemorySize, 98560);
    cudaFuncSetAttribute(k_xproj16, cudaFuncAttributeMaxDynamicSharedMemorySize, 92160);
    cudaFuncSetAttribute(k_rnn<LSEQ>, cudaFuncAttributeMaxDynamicSharedMemorySize, 226816);

    k_prep<<<dim3(8, 8, 6), dim3(32, 8)>>>(Wx, Wh);                  // 0
    k_extract<<<NES, 64>>>(obs, comm);                               // 1
    k_commU<<<dim3(4, 7), 256, 98560>>>(comm_emb, comm_a_emb, cw1, cw3, cw5, cw7); // 2
    k_conv<<<512, dim3(64, 4), 73728>>>();                           // 3 (profiled)
    k_bnfin<<<1, 256>>>(bn_g, bn_b, bx, bh);                         // 4
    k_bnapply<<<1024, 256>>>(cnn_a);                                 // 5
    k_xproj16<<<dim3(1024, 3), 256, 92160>>>();                      // 6
    k_obsM<<<dim3(32, 8), 256>>>(obs_emb, obs_W, obs_a_emb);         // 7
    k_rnn<LSEQ><<<128, 256, 226816>>>();                             // 8
    k_final<<<dim3(64, 4), 256>>>(lin_W, lin_b, lin_a1, lin_a2, out);// 9
    k_obsout<<<NES, 256>>>(obs_b, obs_a, out);                       // 10
}

// round 16
// speedup vs baseline: 1.5626x; 1.0121x over previous
#include <cuda_runtime.h>
#include <cuda_fp16.h>
#include <math.h>
#include <stdint.h>

// ---------------- problem constants ----------------
#define NES   4096          // E*S
#define VOBS  128
#define KOBS  32
#define H     256
#define LSEQ  32
#define VCOMM 32
#define NL    131072        // NES*LSEQ

// ---------------- device scratch (no allocation allowed) ----------------
__device__ __align__(16) float  g_M[VOBS * KOBS * H];
__device__ __align__(16) float  g_U[32768];
__device__ int    g_idx[NES * KOBS];
__device__ int    g_tok[NES * LSEQ];
__device__ __align__(16) __half g_conv16[NL * H];               // [m=n*32+l][c] half
__device__ __align__(16) float  g_bnPart[512 * 512];
__device__ float  g_bnS[H], g_bnT[H];
__device__ float  g_bxh[768];                                   // bx+bh (r,z), bx (n)
__device__ float  g_bhn[256];                                   // bh (n gate)
__device__ __align__(16) __half g_xproj16[(size_t)NL * 768];    // [m][g*256+j] half (bias folded)
__device__ __align__(16) float  g_h[NES * H];                   // final GRU state
__device__ __align__(16) __half g_W16[2][3 * 65536];            // [0]=Wx^T,[1]=Wh^T flat [768][256]

// ---------------- K: transpose+convert Wx, Wh -> g_W16 half ----------------
__global__ void k_prep(const float* __restrict__ Wx, const float* __restrict__ Wh) {
    __shared__ float t[32][33];
    int mat = blockIdx.z / 3, g = blockIdx.z % 3;
    const float* src = (mat ? Wh : Wx) + g * 65536;   // [k][n]
    __half* dst = g_W16[mat] + g * 65536;             // [n][k]
    int x0 = blockIdx.x * 32, y0 = blockIdx.y * 32;
    int tx = threadIdx.x, ty = threadIdx.y;
    #pragma unroll
    for (int r = 0; r < 32; r += 8)
        t[ty + r][tx] = src[(y0 + ty + r) * 256 + x0 + tx];
    __syncthreads();
    #pragma unroll
    for (int r = 0; r < 32; r += 8)
        dst[(x0 + ty + r) * 256 + y0 + tx] = __float2half(t[tx][ty + r]);
}

// ---------------- K: extract obs indices + comm argmax ----------------
__global__ void k_extract(const float* __restrict__ obs, const float* __restrict__ comm) {
    int m = blockIdx.x;
    int lane = threadIdx.x & 31;
    if (threadIdx.x < 32) {
        const float* o = obs + m * VOBS;
        int base = 0;
        #pragma unroll
        for (int c = 0; c < 4; c++) {
            float v = o[c * 32 + lane];
            unsigned mask = __ballot_sync(0xffffffffu, v > 0.5f);
            if (v > 0.5f) {
                int pos = base + __popc(mask & ((1u << lane) - 1u));
                g_idx[m * KOBS + pos] = c * 32 + lane;
            }
            base += __popc(mask);
        }
    } else {
        int l = lane;
        const float* cm = comm + (m * LSEQ + l) * VCOMM;
        float best = cm[0]; int bi = 0;
        #pragma unroll
        for (int v = 1; v < VCOMM; v++) { float x = cm[v]; if (x > best) { best = x; bi = v; } }
        g_tok[m * LSEQ + l] = bi;
    }
}

// ---------------- K: obs table M ----------------
__global__ void k_obsM(const float* __restrict__ emb, const float* __restrict__ W,
                       const float* __restrict__ a_emb_p) {
    __shared__ float Ps[16][256];
    int k = blockIdx.x, i0 = blockIdx.y * 16;
    float a = a_emb_p[0];
    int tid = threadIdx.x;
    for (int r = tid; r < 16 * 256; r += 256) {
        int i = r >> 8, h = r & 255;
        float v = emb[(i0 + i) * H + h];
        Ps[i][h] = v >= 0.f ? v : a * v;
    }
    __syncthreads();
    float acc[16];
    #pragma unroll
    for (int i = 0; i < 16; i++) acc[i] = 0.f;
    int j = tid;
    const float* Wk = W + (k * H) * H + j;
    for (int h = 0; h < H; h++) {
        float w = Wk[h * H];
        #pragma unroll
        for (int i = 0; i < 16; i++) acc[i] = fmaf(Ps[i][h], w, acc[i]);
    }
    #pragma unroll
    for (int i = 0; i < 16; i++)
        g_M[((i0 + i) * KOBS + k) * H + j] = acc[i];
}

// ---------------- K: conv token table U ----------------
__global__ void k_commU(const float* __restrict__ ce, const float* __restrict__ a_emb_p,
                        const float* __restrict__ w1, const float* __restrict__ w3,
                        const float* __restrict__ w5, const float* __restrict__ w7) {
    extern __shared__ float smc[];
    float* sE = smc;
    float* sW = smc + 8192;
    int g = blockIdx.x, d = blockIdx.y;
    int ks = 2 * g + 1;
    if (d >= ks) return;
    const float* w = (g == 0) ? w1 : (g == 1) ? w3 : (g == 2) ? w5 : w7;
    int tid = threadIdx.x;
    float a = a_emb_p[0];
    for (int v = tid; v < 8192; v += 256) {
        float e = ce[v];
        sE[v] = e >= 0.f ? e : a * e;
    }
    for (int v = tid; v < 16384; v += 256) {
        int cg = v >> 8, h = v & 255;
        sW[cg * 257 + h] = w[(cg * 256 + h) * ks + d];
    }
    __syncthreads();
    int cg = tid & 63, t0 = (tid >> 6) * 8;
    float acc[8];
    #pragma unroll
    for (int t = 0; t < 8; t++) acc[t] = 0.f;
    for (int h = 0; h < 256; h++) {
        float wv = sW[cg * 257 + h];
        #pragma unroll
        for (int t = 0; t < 8; t++) acc[t] = fmaf(sE[(t0 + t) * 256 + h], wv, acc[t]);
    }
    int segoff = (g == 0) ? 0 : (g == 1) ? 2048 : (g == 2) ? 8192 : 18432;
    #pragma unroll
    for (int t = 0; t < 8; t++)
        g_U[segoff + (d * 32 + t0 + t) * 64 + cg] = acc[t];
}

// ---------------- K: conv via half table lookups (fp32 tap accumulation) ----------------
__global__ void k_conv() {
    extern __shared__ float sm[];
    __half* sUh = (__half*)sm;                         // 32768 halves = 65536 B
    float* sRed = (float*)((char*)sm + 65536);         // 2048 floats
    __shared__ int sTok[256];
    int tx = threadIdx.x, ty = threadIdx.y;
    int tid = ty * 64 + tx;
    int n0 = blockIdx.x * 8;
    const float4* gU4 = (const float4*)g_U;
    uint2* sU2 = (uint2*)sUh;
    for (int v = tid; v < 8192; v += 256) {
        float4 f = gU4[v];
        __half2 h0 = __floats2half2_rn(f.x, f.y);
        __half2 h1 = __floats2half2_rn(f.z, f.w);
        uint2 pk; pk.x = *(uint*)&h0; pk.y = *(uint*)&h1;
        sU2[v] = pk;
    }
    if (tid < 256) sTok[tid] = g_tok[n0 * LSEQ + tid];
    __syncthreads();

    int g = tx >> 4, ks = 2 * g + 1, pad = g;
    int seg4 = (g == 0) ? 0 : (g == 1) ? 512 : (g == 2) ? 2048 : 4608;
    int cm = tx & 15;
    float lsum[4] = {0, 0, 0, 0}, lsq[4] = {0, 0, 0, 0};

    for (int half = 0; half < 2; half++) {
        int nl = ty + 4 * half;
        int n = n0 + nl;
        const int* tk = sTok + nl * LSEQ;
        for (int l = 0; l < LSEQ; l++) {
            float a0 = 0.f, a1 = 0.f, a2 = 0.f, a3 = 0.f;
            #pragma unroll
            for (int d = 0; d < 7; d++) {
                int lp = l + d - pad;
                if (d < ks && lp >= 0 && lp < LSEQ) {
                    uint2 u = sU2[seg4 + (d * 32 + tk[lp]) * 16 + cm];
                    float2 f0 = __half22float2(*(__half2*)&u.x);
                    float2 f1 = __half22float2(*(__half2*)&u.y);
                    a0 += f0.x; a1 += f0.y; a2 += f1.x; a3 += f1.y;
                }
            }
            __half2 p0 = __floats2half2_rn(a0, a1);
            __half2 p1 = __floats2half2_rn(a2, a3);
            uint2 pk; pk.x = *(uint*)&p0; pk.y = *(uint*)&p1;
            *(uint2*)&g_conv16[(size_t)(n * LSEQ + l) * 256 + tx * 4] = pk;
            lsum[0] += a0; lsum[1] += a1; lsum[2] += a2; lsum[3] += a3;
            lsq[0] += a0 * a0; lsq[1] += a1 * a1; lsq[2] += a2 * a2; lsq[3] += a3 * a3;
        }
    }
    #pragma unroll
    for (int e = 0; e < 4; e++) {
        sRed[ty * 512 + 4 * tx + e]       = lsum[e];
        sRed[ty * 512 + 256 + 4 * tx + e] = lsq[e];
    }
    __syncthreads();
    if (tid < 256) {
        float s = sRed[tid] + sRed[512 + tid] + sRed[1024 + tid] + sRed[1536 + tid];
        float q = sRed[256 + tid] + sRed[768 + tid] + sRed[1280 + tid] + sRed[1792 + tid];
        g_bnPart[blockIdx.x * 512 + tid]       = s;
        g_bnPart[blockIdx.x * 512 + 256 + tid] = q;
    }
}

// ---------------- K: finalize BN + bias folding (4-way ILP) ----------------
__global__ void k_bnfin(const float* __restrict__ bn_g, const float* __restrict__ bn_b,
                        const float* __restrict__ bx, const float* __restrict__ bh) {
    int c = threadIdx.x;
    double s0 = 0, s1 = 0, s2 = 0, s3 = 0;
    double q0 = 0, q1 = 0, q2 = 0, q3 = 0;
    for (int b = 0; b < 512; b += 4) {
        s0 += (double)g_bnPart[(b + 0) * 512 + c];
        s1 += (double)g_bnPart[(b + 1) * 512 + c];
        s2 += (double)g_bnPart[(b + 2) * 512 + c];
        s3 += (double)g_bnPart[(b + 3) * 512 + c];
        q0 += (double)g_bnPart[(b + 0) * 512 + 256 + c];
        q1 += (double)g_bnPart[(b + 1) * 512 + 256 + c];
        q2 += (double)g_bnPart[(b + 2) * 512 + 256 + c];
        q3 += (double)g_bnPart[(b + 3) * 512 + 256 + c];
    }
    double s = (s0 + s1) + (s2 + s3);
    double q = (q0 + q1) + (q2 + q3);
    double mean = s / (double)NL;
    double var  = q / (double)NL - mean * mean;
    float sc = (float)((double)bn_g[c] / sqrt(var + 1e-5));
    g_bnS[c] = sc;
    g_bnT[c] = bn_b[c] - sc * (float)mean;
    g_bxh[c]       = bx[c]       + bh[c];
    g_bxh[256 + c] = bx[256 + c] + bh[256 + c];
    g_bxh[512 + c] = bx[512 + c];
    g_bhn[c]       = bh[512 + c];
}

// ---------------- K: apply BN+prelu to g_conv16 in place ----------------
__global__ void k_bnapply(const float* __restrict__ cnn_a_p) {
    float ca = cnn_a_p[0];
    uint4* p = (uint4*)g_conv16;
    int base = blockIdx.x * 4096 + threadIdx.x;
    #pragma unroll 4
    for (int k = 0; k < 16; k++) {
        int i = base + k * 256;
        uint4 v = p[i];
        int c0 = (i & 31) * 8;
        uint rv[4] = {v.x, v.y, v.z, v.w};
        #pragma unroll
        for (int u = 0; u < 4; u++) {
            __half2 hv = *(__half2*)&rv[u];
            float2 f = __half22float2(hv);
            int c = c0 + 2 * u;
            float x0 = fmaf(g_bnS[c],     f.x, g_bnT[c]);
            x0 = x0 >= 0.f ? x0 : ca * x0;
            float x1 = fmaf(g_bnS[c + 1], f.y, g_bnT[c + 1]);
            x1 = x1 >= 0.f ? x1 : ca * x1;
            __half2 o = __floats2half2_rn(x0, x1);
            rv[u] = *(uint*)&o;
        }
        v.x = rv[0]; v.y = rv[1]; v.z = rv[2]; v.w = rv[3];
        p[i] = v;
    }
}

// ---------------- K: fp16 mma xproj GEMM, CTA 128x256, K-chunk 64 (4 chunks), 3-stage ----------------
__global__ void __launch_bounds__(256, 1) k_xproj16() {
    extern __shared__ __align__(16) __half xsm[];
    __half* As = xsm;                  // [3][128][72]  55296 B
    __half* Bs = xsm + 3 * 9216;       // [3][256][72] 110592 B
    int tid = threadIdx.x, lane = tid & 31, wid = tid >> 5;
    int wr = wid & 1, wc = wid >> 1;   // wr 0..1 (64 rows), wc 0..3 (64 cols)
    int m0 = blockIdx.x * 128, nc0 = blockIdx.y * 256;
    const __half* Ag = g_conv16 + (size_t)m0 * 256;
    const __half* Bg = g_W16[0] + (size_t)nc0 * 256;

    float acc[4][8][4];
    #pragma unroll
    for (int i = 0; i < 4; i++)
        #pragma unroll
        for (int j = 0; j < 8; j++)
            #pragma unroll
            for (int q = 0; q < 4; q++) acc[i][j][q] = 0.f;

    #define CPX(s_, k0_) {                                                                 \
        _Pragma("unroll")                                                                  \
        for (int it = 0; it < 2; it++) {                                                   \
            int idx = tid + it * 256;                                                      \
            int row = idx >> 2, kc = idx & 3;                                              \
            uint32_t da = (uint32_t)__cvta_generic_to_shared(                              \
                &As[(s_) * 9216 + row * 72 + kc * 16]);                                    \
            asm volatile("cp.async.cg.shared.global [%0], [%1], 16;"                       \
                :: "r"(da), "l"(Ag + (size_t)row * 256 + (k0_) + kc * 16));                \
            asm volatile("cp.async.cg.shared.global [%0], [%1], 16;"                       \
                :: "r"(da + 16), "l"(Ag + (size_t)row * 256 + (k0_) + kc * 16 + 8));       \
        }                                                                                  \
        _Pragma("unroll")                                                                  \
        for (int it = 0; it < 4; it++) {                                                   \
            int idx = tid + it * 256;                                                      \
            int row = idx >> 2, kc = idx & 3;                                              \
            uint32_t db = (uint32_t)__cvta_generic_to_shared(                              \
                &Bs[(s_) * 18432 + row * 72 + kc * 16]);                                   \
            asm volatile("cp.async.cg.shared.global [%0], [%1], 16;"                       \
                :: "r"(db), "l"(Bg + (size_t)row * 256 + (k0_) + kc * 16));                \
            asm volatile("cp.async.cg.shared.global [%0], [%1], 16;"                       \
                :: "r"(db + 16), "l"(Bg + (size_t)row * 256 + (k0_) + kc * 16 + 8));       \
        }                                                                                  \
        asm volatile("cp.async.commit_group;" ::: "memory");                               \
    }

    CPX(0, 0);
    CPX(1, 64);

    #pragma unroll 1
    for (int c = 0; c < 4; c++) {
        if (c < 3) { asm volatile("cp.async.wait_group 1;" ::: "memory"); }
        else       { asm volatile("cp.async.wait_group 0;" ::: "memory"); }
        __syncthreads();
        if (c < 2) {
            int s2 = (c + 2) % 3;
            CPX(s2, (c + 2) * 64);
        }
        int st = c % 3;
        __half* Ast = As + st * 9216;
        __half* Bst = Bs + st * 18432;
        #pragma unroll
        for (int kk = 0; kk < 4; kk++) {
            uint a[4][4], bb[8][2];
            #pragma unroll
            for (int mi = 0; mi < 4; mi++) {
                uint32_t ad = (uint32_t)__cvta_generic_to_shared(
                    &Ast[(wr * 64 + mi * 16 + (lane & 15)) * 72 + kk * 16 + (lane >> 4) * 8]);
                asm volatile("ldmatrix.sync.aligned.m8n8.x4.shared.b16 {%0,%1,%2,%3}, [%4];"
                    : "=r"(a[mi][0]), "=r"(a[mi][1]), "=r"(a[mi][2]), "=r"(a[mi][3]) : "r"(ad));
            }
            #pragma unroll
            for (int p = 0; p < 4; p++) {
                uint32_t bd = (uint32_t)__cvta_generic_to_shared(
                    &Bst[(wc * 64 + p * 16 + ((lane >> 4) << 3) + (lane & 7)) * 72 +
                         kk * 16 + ((lane >> 3) & 1) * 8]);
                uint r0, r1, r2, r3;
                asm volatile("ldmatrix.sync.aligned.m8n8.x4.shared.b16 {%0,%1,%2,%3}, [%4];"
                    : "=r"(r0), "=r"(r1), "=r"(r2), "=r"(r3) : "r"(bd));
                bb[2 * p][0] = r0; bb[2 * p][1] = r1;
                bb[2 * p + 1][0] = r2; bb[2 * p + 1][1] = r3;
            }
            #pragma unroll
            for (int mi = 0; mi < 4; mi++)
                #pragma unroll
                for (int ni = 0; ni < 8; ni++)
                    asm volatile("mma.sync.aligned.m16n8k16.row.col.f32.f16.f16.f32 "
                        "{%0,%1,%2,%3}, {%4,%5,%6,%7}, {%8,%9}, {%0,%1,%2,%3};"
                        : "+f"(acc[mi][ni][0]), "+f"(acc[mi][ni][1]),
                          "+f"(acc[mi][ni][2]), "+f"(acc[mi][ni][3])
                        : "r"(a[mi][0]), "r"(a[mi][1]), "r"(a[mi][2]), "r"(a[mi][3]),
                          "r"(bb[ni][0]), "r"(bb[ni][1]));
        }
    }

    #pragma unroll
    for (int mi = 0; mi < 4; mi++) {
        int m = m0 + wr * 64 + mi * 16 + (lane >> 2);
        #pragma unroll
        for (int ni = 0; ni < 8; ni++) {
            int n = nc0 + wc * 64 + ni * 8 + (lane & 3) * 2;
            float2 bv = *(const float2*)&g_bxh[n];
            __half2 v0 = __floats2half2_rn(acc[mi][ni][0] + bv.x, acc[mi][ni][1] + bv.y);
            __half2 v1 = __floats2half2_rn(acc[mi][ni][2] + bv.x, acc[mi][ni][3] + bv.y);
            *(__half2*)&g_xproj16[(size_t)m * 768 + n] = v0;
            *(__half2*)&g_xproj16[(size_t)(m + 8) * 768 + n] = v1;
        }
    }
    #undef CPX
}

// ---------------- K: persistent fused GRU — 2 K-slices per phase (8 phases/step) ----------------
// 256 threads / 8 warps, R10 sync discipline. Bt [2][2][768][24]: double-buffered
// slice-PAIRS (48 MMA/warp between barriers). Gates read g_xproj16 from L2 directly;
// h fp32 carry in registers.
template<int STEPS>
__global__ void __launch_bounds__(256, 1) k_rnn() {
    extern __shared__ __align__(16) char rsm[];
    __half* hH = (__half*)rsm;                          // [32][264]        16896 B
    __half* Gs = (__half*)(rsm + 16896);                // [32][776] fp16   49664 B
    __half* Bt = (__half*)(rsm + 66560);                // [2][2][768][24] 147456 B
    // total 214016 B

    int tid = threadIdx.x, lane = tid & 31, w = tid >> 5;
    int n0 = blockIdx.x * 32;
    const __half* whR = g_W16[1];                       // [768][256]

    for (int i = tid; i < 32 * 264; i += 256) hH[i] = __float2half(0.f);
    __syncthreads();

    int gr_r = tid >> 3;                // gate row 0..31
    int gs   = (tid & 7) * 4;           // gate col base: j = gs + 32q
    float hreg[32];
    #pragma unroll
    for (int i = 0; i < 32; i++) hreg[i] = 0.f;

    // CPB(g_): load K-slices 2*(g_&7), 2*(g_&7)+1 into buffer (g_&1), one commit group.
    #define CPB(g_) {                                                                      \
        int b_ = (g_) & 1, p_ = (g_) & 7;                                                  \
        _Pragma("unroll")                                                                  \
        for (int s_ = 0; s_ < 2; s_++) {                                                   \
            int kcs_ = 2 * p_ + s_;                                                        \
            _Pragma("unroll")                                                              \
            for (int i = 0; i < 6; i++) {                                                  \
                int idx = tid + i * 256;                                                   \
                int n = idx >> 1, seg = idx & 1;                                           \
                uint32_t dst = (uint32_t)__cvta_generic_to_shared(                         \
                    &Bt[(b_ * 2 + s_) * 18432 + n * 24 + seg * 8]);                        \
                const __half* src = whR + (size_t)n * 256 + kcs_ * 16 + seg * 8;           \
                asm volatile("cp.async.cg.shared.global [%0], [%1], 16;" :: "r"(dst), "l"(src)); \
            }                                                                              \
        }                                                                                  \
        asm volatile("cp.async.commit_group;" ::: "memory");                               \
    }

    CPB(0);

    #pragma unroll 1
    for (int l = 0; l < STEPS; l++) {
        float acc[2][12][4];
        #pragma unroll
        for (int mi = 0; mi < 2; mi++)
            #pragma unroll
            for (int ni = 0; ni < 12; ni++)
                #pragma unroll
                for (int q = 0; q < 4; q++) acc[mi][ni][q] = 0.f;

        #pragma unroll 1
        for (int p = 0; p < 8; p++) {
            int gp = l * 8 + p;
            if (gp + 1 < STEPS * 8) {
                CPB(gp + 1);
                asm volatile("cp.async.wait_group 1;" ::: "memory");
            } else {
                asm volatile("cp.async.wait_group 0;" ::: "memory");
            }
            __syncthreads();
            int b = gp & 1;
            #pragma unroll
            for (int s = 0; s < 2; s++) {
                int kc = 2 * p + s;
                uint af[2][4];
                #pragma unroll
                for (int mi = 0; mi < 2; mi++) {
                    uint32_t ad = (uint32_t)__cvta_generic_to_shared(
                        &hH[(mi * 16 + (lane & 15)) * 264 + kc * 16 + (lane >> 4) * 8]);
                    asm volatile("ldmatrix.sync.aligned.m8n8.x4.shared.b16 {%0,%1,%2,%3}, [%4];"
                        : "=r"(af[mi][0]), "=r"(af[mi][1]), "=r"(af[mi][2]), "=r"(af[mi][3]) : "r"(ad));
                }
                uint bfr[12][2];
                #pragma unroll
                for (int pp = 0; pp < 6; pp++) {
                    uint32_t bd = (uint32_t)__cvta_generic_to_shared(
                        &Bt[(b * 2 + s) * 18432 +
                            (w * 96 + pp * 16 + ((lane >> 4) << 3) + (lane & 7)) * 24 +
                            ((lane >> 3) & 1) * 8]);
                    uint r0, r1, r2, r3;
                    asm volatile("ldmatrix.sync.aligned.m8n8.x4.shared.b16 {%0,%1,%2,%3}, [%4];"
                        : "=r"(r0), "=r"(r1), "=r"(r2), "=r"(r3) : "r"(bd));
                    bfr[2 * pp][0] = r0;     bfr[2 * pp][1] = r1;
                    bfr[2 * pp + 1][0] = r2; bfr[2 * pp + 1][1] = r3;
                }
                #pragma unroll
                for (int mi = 0; mi < 2; mi++)
                    #pragma unroll
                    for (int ni = 0; ni < 12; ni++)
                        asm volatile("mma.sync.aligned.m16n8k16.row.col.f32.f16.f16.f32 "
                            "{%0,%1,%2,%3}, {%4,%5,%6,%7}, {%8,%9}, {%0,%1,%2,%3};"
                            : "+f"(acc[mi][ni][0]), "+f"(acc[mi][ni][1]),
                              "+f"(acc[mi][ni][2]), "+f"(acc[mi][ni][3])
                            : "r"(af[mi][0]), "r"(af[mi][1]), "r"(af[mi][2]), "r"(af[mi][3]),
                              "r"(bfr[ni][0]), "r"(bfr[ni][1]));
            }
        }

        // acc -> Gs (fp16)
        #pragma unroll
        for (int mi = 0; mi < 2; mi++)
            #pragma unroll
            for (int ni = 0; ni < 12; ni++) {
                int r = mi * 16 + (lane >> 2);
                int c = w * 96 + ni * 8 + (lane & 3) * 2;
                __half2 h0 = __floats2half2_rn(acc[mi][ni][0], acc[mi][ni][1]);
                __half2 h1 = __floats2half2_rn(acc[mi][ni][2], acc[mi][ni][3]);
                *(__half2*)&Gs[r * 776 + c]       = h0;
                *(__half2*)&Gs[(r + 8) * 776 + c] = h1;
            }
        __syncthreads();

        // gates: thread -> row gr_r, cols gs + 32q + {0..3}; xp streamed from L2
        {
            const __half* xp = g_xproj16 + ((size_t)(n0 + gr_r) * 32 + l) * 768;
            #pragma unroll
            for (int q = 0; q < 8; q++) {
                int j = gs + 32 * q;
                uint2 vr = __ldg((const uint2*)&xp[j]);
                uint2 vz = __ldg((const uint2*)&xp[256 + j]);
                uint2 vn = __ldg((const uint2*)&xp[512 + j]);
                uint2 wr2 = *(const uint2*)&Gs[gr_r * 776 + j];
                uint2 wz2 = *(const uint2*)&Gs[gr_r * 776 + 256 + j];
                uint2 wn2 = *(const uint2*)&Gs[gr_r * 776 + 512 + j];
                float2 xr01 = __half22float2(*(__half2*)&vr.x);
                float2 xr23 = __half22float2(*(__half2*)&vr.y);
                float2 xz01 = __half22float2(*(__half2*)&vz.x);
                float2 xz23 = __half22float2(*(__half2*)&vz.y);
                float2 xn01 = __half22float2(*(__half2*)&vn.x);
                float2 xn23 = __half22float2(*(__half2*)&vn.y);
                float2 gr01 = __half22float2(*(__half2*)&wr2.x);
                float2 gr23 = __half22float2(*(__half2*)&wr2.y);
                float2 gz01 = __half22float2(*(__half2*)&wz2.x);
                float2 gz23 = __half22float2(*(__half2*)&wz2.y);
                float2 gn01 = __half22float2(*(__half2*)&wn2.x);
                float2 gn23 = __half22float2(*(__half2*)&wn2.y);
                float4 bn4 = *(const float4*)&g_bhn[j];
                float xr[4] = {xr01.x, xr01.y, xr23.x, xr23.y};
                float xz[4] = {xz01.x, xz01.y, xz23.x, xz23.y};
                float xn[4] = {xn01.x, xn01.y, xn23.x, xn23.y};
                float gr[4] = {gr01.x, gr01.y, gr23.x, gr23.y};
                float gz[4] = {gz01.x, gz01.y, gz23.x, gz23.y};
                float gn[4] = {gn01.x + bn4.x, gn01.y + bn4.y, gn23.x + bn4.z, gn23.y + bn4.w};
                float hn[4];
                #pragma unroll
                for (int e = 0; e < 4; e++) {
                    float h = hreg[4 * q + e];
                    float rr = __fdividef(1.f, 1.f + __expf(-(xr[e] + gr[e])));
                    float zz = __fdividef(1.f, 1.f + __expf(-(xz[e] + gz[e])));
                    float arg = xn[e] + rr * gn[e];
                    float e2 = __expf(2.f * arg);
                    float th = 1.f - __fdividef(2.f, e2 + 1.f);
                    hn[e] = th + zz * (h - th);
                    hreg[4 * q + e] = hn[e];
                }
                __half2 hh0 = __floats2half2_rn(hn[0], hn[1]);
                __half2 hh1 = __floats2half2_rn(hn[2], hn[3]);
                uint2 pk; pk.x = *(uint*)&hh0; pk.y = *(uint*)&hh1;
                *(uint2*)&hH[gr_r * 264 + j] = pk;
            }
        }
        __syncthreads();
    }
    #pragma unroll
    for (int q = 0; q < 8; q++) {
        *(float4*)&g_h[(size_t)(n0 + gr_r) * 256 + gs + 32 * q] =
            make_float4(hreg[4 * q], hreg[4 * q + 1], hreg[4 * q + 2], hreg[4 * q + 3]);
    }
    #undef CPB
}

// ---------------- K: final linear on c-path ----------------
__global__ void k_final(const float* __restrict__ Wl, const float* __restrict__ bl,
                        const float* __restrict__ a1p, const float* __restrict__ a2p,
                        float* __restrict__ out) {
    __shared__ float As[16 * 68];
    __shared__ float Bs[16 * 64];
    int m0 = blockIdx.x * 64;
    int j0 = blockIdx.y * 64;
    float a1 = a1p[0], a2 = a2p[0];
    const float* A = g_h;
    int tid = threadIdx.x;
    int tx = tid & 15, ty = tid >> 4;
    float acc[4][4];
    #pragma unroll
    for (int i = 0; i < 4; i++)
        #pragma unroll
        for (int j = 0; j < 4; j++) acc[i][j] = 0.f;

    for (int k0 = 0; k0 < H; k0 += 16) {
        int row = tid >> 2, segc = tid & 3;
        float4 a4 = *(const float4*)&A[(m0 + row) * H + k0 + 4 * segc];
        float av[4] = {a4.x, a4.y, a4.z, a4.w};
        #pragma unroll
        for (int e = 0; e < 4; e++) {
            float x = av[e];
            As[(4 * segc + e) * 68 + row] = x >= 0.f ? x : a1 * x;
        }
        int rowk = tid >> 4, jc = tid & 15;
        float4 b4 = *(const float4*)&Wl[(k0 + rowk) * H + j0 + 4 * jc];
        *(float4*)&Bs[rowk * 64 + 4 * jc] = b4;
        __syncthreads();
        #pragma unroll
        for (int k = 0; k < 16; k++) {
            float a[4], b[4];
            *(float4*)a = *(const float4*)&As[k * 68 + ty * 4];
            *(float4*)b = *(const float4*)&Bs[k * 64 + tx * 4];
            #pragma unroll
            for (int i = 0; i < 4; i++)
                #pragma unroll
                for (int j = 0; j < 4; j++)
                    acc[i][j] = fmaf(a[i], b[j], acc[i][j]);
        }
        __syncthreads();
    }
    #pragma unroll
    for (int i = 0; i < 4; i++) {
        int m = m0 + ty * 4 + i;
        #pragma unroll
        for (int j = 0; j < 4; j++) {
            int jj = j0 + tx * 4 + j;
            float v = acc[i][j] + bl[jj];
            v = v >= 0.f ? v : a2 * v;
            out[m * 512 + 256 + jj] = v;
        }
    }
}

// ---------------- K: obs output ----------------
__global__ void k_obsout(const float* __restrict__ obs_b, const float* __restrict__ obs_a_p,
                         float* __restrict__ out) {
    int m = blockIdx.x;
    int j = threadIdx.x;
    __shared__ int si[KOBS];
    if (j < KOBS) si[j] = g_idx[m * KOBS + j];
    __syncthreads();
    float acc = obs_b[j];
    #pragma unroll
    for (int k = 0; k < KOBS; k++)
        acc += g_M[(si[k] * KOBS + k) * H + j];
    float a = obs_a_p[0];
    out[m * 512 + j] = acc >= 0.f ? acc : a * acc;
}

// ---------------- host launch ----------------
extern "C" void kernel_launch(void* const* d_in, const int* in_sizes, int n_in,
                              void* d_out, int out_size) {
    const float* obs        = (const float*)d_in[0];
    const float* comm       = (const float*)d_in[1];
    const float* obs_emb    = (const float*)d_in[2];
    const float* obs_a_emb  = (const float*)d_in[3];
    const float* obs_W      = (const float*)d_in[4];
    const float* obs_b      = (const float*)d_in[5];
    const float* obs_a      = (const float*)d_in[6];
    const float* comm_emb   = (const float*)d_in[7];
    const float* comm_a_emb = (const float*)d_in[8];
    const float* cw1        = (const float*)d_in[9];
    const float* cw3        = (const float*)d_in[11];
    const float* cw5        = (const float*)d_in[13];
    const float* cw7        = (const float*)d_in[15];
    const float* bn_g       = (const float*)d_in[17];
    const float* bn_b       = (const float*)d_in[18];
    const float* cnn_a      = (const float*)d_in[19];
    const float* Wx         = (const float*)d_in[20];
    const float* bx         = (const float*)d_in[21];
    const float* Wh         = (const float*)d_in[22];
    const float* bh         = (const float*)d_in[23];
    const float* lin_a1     = (const float*)d_in[24];
    const float* lin_W      = (const float*)d_in[25];
    const float* lin_b      = (const float*)d_in[26];
    const float* lin_a2     = (const float*)d_in[27];
    float* out = (float*)d_out;

    cudaFuncSetAttribute(k_conv,    cudaFuncAttributeMaxDynamicSharedMemorySize, 73728);
    cudaFuncSetAttribute(k_commU,   cudaFuncAttributeMaxDynamicSharedMemorySize, 98560);
    cudaFuncSetAttribute(k_xproj16, cudaFuncAttributeMaxDynamicSharedMemorySize, 165888);
    cudaFuncSetAttribute(k_rnn<LSEQ>, cudaFuncAttributeMaxDynamicSharedMemorySize, 214016);

    k_prep<<<dim3(8, 8, 6), dim3(32, 8)>>>(Wx, Wh);                  // 0
    k_extract<<<NES, 64>>>(obs, comm);                               // 1
    k_commU<<<dim3(4, 7), 256, 98560>>>(comm_emb, comm_a_emb, cw1, cw3, cw5, cw7); // 2
    k_conv<<<512, dim3(64, 4), 73728>>>();                           // 3 (profiled)
    k_bnfin<<<1, 256>>>(bn_g, bn_b, bx, bh);                         // 4
    k_bnapply<<<1024, 256>>>(cnn_a);                                 // 5
    k_xproj16<<<dim3(1024, 3), 256, 165888>>>();                     // 6
    k_obsM<<<dim3(32, 8), 256>>>(obs_emb, obs_W, obs_a_emb);         // 7
    k_rnn<LSEQ><<<128, 256, 214016>>>();                             // 8
    k_final<<<dim3(64, 4), 256>>>(lin_W, lin_b, lin_a1, lin_a2, out);// 9
    k_obsout<<<NES, 256>>>(obs_b, obs_a, out);                       // 10
}